// round 9
// baseline (speedup 1.0000x reference)
#include <cuda_runtime.h>
#include <cuda_fp16.h>
#include <cstdint>
#include <cstddef>

#define BB   2048
#define TT   128
#define FF   64
#define HH   256
#define G3   768
#define OL   32
#define FCH  256
#define BM   16
#define ASP  10          // float2 pairs per As row (8 used + 2 pad -> 80B rows, 16B aligned)

// ---- device scratch ----
__device__ __half g_hsh[(size_t)TT * BB * HH];          // [t][b][j] fp16 (ctx source)
__device__ float4 g_W6a[160 * 256];                     // enc packed weights (2k per q)
__device__ float2 g_W6b[160 * 256];
__device__ float4 g_D6a[128 * 256];                     // dec_Whh packed
__device__ float2 g_D6b[128 * 256];
__device__ float2 g_F2 [128 * 256];                     // fc1 packed
__device__ float  g_brz[512], g_bin[256], g_bhn[256];
__device__ float  g_dbrz[512], g_dbin[256], g_dbhn[256];
__device__ float  g_Abt[(size_t)BB * TT];
__device__ float  g_Cbt[(size_t)BB * TT];
__device__ float  g_prev[BB];

typedef unsigned long long u64;

__device__ __forceinline__ void fma2(u64 &d, u64 a, u64 b) {
    asm("fma.rn.f32x2 %0, %1, %2, %0;" : "+l"(d) : "l"(a), "l"(b));
}
__device__ __forceinline__ u64 pack2(float w) {
    u64 r; unsigned int u = __float_as_uint(w);
    asm("mov.b64 %0, {%1,%1};" : "=l"(r) : "r"(u));
    return r;
}
__device__ __forceinline__ float2 u2f(u64 v) {
    float2 r;
    asm("mov.b64 {%0, %1}, %2;" : "=f"(r.x), "=f"(r.y) : "l"(v));
    return r;
}
// two fp16 (packed in u32) -> packed f32x2 (exact widening)
__device__ __forceinline__ u64 hfp(unsigned v) {
    __half2 h2 = *reinterpret_cast<__half2*>(&v);
    float2 f = __half22float2(h2);
    u64 r;
    asm("mov.b64 %0, {%1,%2};" : "=l"(r) : "f"(f.x), "f"(f.y));
    return r;
}
__device__ __forceinline__ float sigf(float x) { return 1.f / (1.f + __expf(-x)); }

// ---- prep: packed weight streams + bias folding + prev0 ----
__global__ void prep_kernel(const float* __restrict__ x,
                            const float* __restrict__ eWih, const float* __restrict__ eWhh,
                            const float* __restrict__ ebih, const float* __restrict__ ebhh,
                            const float* __restrict__ dWhh,
                            const float* __restrict__ dbih, const float* __restrict__ dbhh,
                            const float* __restrict__ fc1W) {
    const int stride = gridDim.x * blockDim.x;
    const int id = blockIdx.x * blockDim.x + threadIdx.x;
    for (int i = id; i < 160 * 256; i += stride) {
        int q = i >> 8, j = i & 255;
        float wr0, wz0, w30, wr1, wz1, w31;
        if (q < 32) {
            int k0 = 2 * q, k1 = k0 + 1;
            wr0 = eWih[j * 64 + k0];         wr1 = eWih[j * 64 + k1];
            wz0 = eWih[(256 + j) * 64 + k0]; wz1 = eWih[(256 + j) * 64 + k1];
            w30 = eWih[(512 + j) * 64 + k0]; w31 = eWih[(512 + j) * 64 + k1];
        } else {
            int k0 = 2 * q - 64, k1 = k0 + 1;
            wr0 = eWhh[j * 256 + k0];         wr1 = eWhh[j * 256 + k1];
            wz0 = eWhh[(256 + j) * 256 + k0]; wz1 = eWhh[(256 + j) * 256 + k1];
            w30 = eWhh[(512 + j) * 256 + k0]; w31 = eWhh[(512 + j) * 256 + k1];
        }
        g_W6a[i] = make_float4(wr0, wz0, w30, wr1);
        g_W6b[i] = make_float2(wz1, w31);
    }
    for (int i = id; i < 128 * 256; i += stride) {
        int q = i >> 8, j = i & 255;
        int k0 = 2 * q, k1 = k0 + 1;
        g_D6a[i] = make_float4(dWhh[j * 256 + k0], dWhh[(256 + j) * 256 + k0],
                               dWhh[(512 + j) * 256 + k0], dWhh[j * 256 + k1]);
        g_D6b[i] = make_float2(dWhh[(256 + j) * 256 + k1], dWhh[(512 + j) * 256 + k1]);
        g_F2[i]  = make_float2(fc1W[j * 256 + k0], fc1W[j * 256 + k1]);
    }
    for (int i = id; i < 512; i += stride) {
        g_brz[i]  = ebih[i] + ebhh[i];
        g_dbrz[i] = dbih[i] + dbhh[i];
    }
    for (int i = id; i < 256; i += stride) {
        g_bin[i]  = ebih[512 + i];  g_bhn[i]  = ebhh[512 + i];
        g_dbin[i] = dbih[512 + i];  g_dbhn[i] = dbhh[512 + i];
    }
    for (int i = id; i < BB; i += stride)
        g_prev[i] = x[((size_t)i * TT + (TT - 1)) * FF];
}

// 2-k FMA body, 512-thread version: this thread covers 4 pairs selected by `half`
#define ENC_BODY(K0, AS) do {                                                              \
    const double2* _av0 = reinterpret_cast<const double2*>(As + (K0) * ASP) + 2 * half;    \
    const double2* _av1 = reinterpret_cast<const double2*>(As + ((K0) + 1) * ASP) + 2 * half; \
    u64 _p00 = pack2(wa.x), _p01 = pack2(wa.y), _p02 = pack2(wa.z);                        \
    u64 _p10 = pack2(wa.w), _p11 = pack2(wb.x), _p12 = pack2(wb.y);                        \
    _Pragma("unroll")                                                                      \
    for (int _h = 0; _h < 2; _h++) {                                                       \
        double2 _d0 = _av0[_h], _d1 = _av1[_h];                                            \
        u64 _a00 = __double_as_longlong(_d0.x), _a01 = __double_as_longlong(_d0.y);        \
        u64 _a10 = __double_as_longlong(_d1.x), _a11 = __double_as_longlong(_d1.y);        \
        fma2(aR[2*_h],   _p00, _a00); fma2(aZ[2*_h],   _p01, _a00); fma2(AS[2*_h],   _p02, _a00); \
        fma2(aR[2*_h+1], _p00, _a01); fma2(aZ[2*_h+1], _p01, _a01); fma2(AS[2*_h+1], _p02, _a01); \
        fma2(aR[2*_h],   _p10, _a10); fma2(aZ[2*_h],   _p11, _a10); fma2(AS[2*_h],   _p12, _a10); \
        fma2(aR[2*_h+1], _p10, _a11); fma2(aZ[2*_h+1], _p11, _a11); fma2(AS[2*_h+1], _p12, _a11); \
    }                                                                                      \
} while (0)

// ---- persistent encoder: 512 threads, each thread owns 4 batch pairs of its gate rows ----
__global__ void __launch_bounds__(512, 1) enc_all_kernel(const float* __restrict__ x,
                                                         const float* __restrict__ h0,
                                                         const float* __restrict__ wq,
                                                         const float* __restrict__ bq) {
    __shared__ float2 As[320 * ASP];              // x rows 0..63, h rows 64..319
    __shared__ float2 redA[16 * 4], redC[16 * 4]; // [warp][local pair]
    float* Asf = reinterpret_cast<float*>(As);
    const int tid = threadIdx.x;       // 0..511
    const int j = tid & 255;           // gate/hidden index
    const int half = tid >> 8;         // 0: pairs 0-3, 1: pairs 4-7
    const int wid = tid >> 5, lane = tid & 31;
    const int B0 = blockIdx.x * BM;

    for (int i = tid; i < BM * HH; i += 512) {
        int b = i >> 8, k = i & 255;
        Asf[((64 + k) * ASP + (b >> 1)) * 2 + (b & 1)] = h0[(size_t)(B0 + b) * HH + k];
    }
    for (int i = tid; i < BM * FF; i += 512) {
        int b = i >> 6, k = i & 63;
        Asf[(k * ASP + (b >> 1)) * 2 + (b & 1)] = x[((size_t)(B0 + b) * TT + 0) * FF + k];
    }
    const float brz1 = g_brz[j], brz2 = g_brz[256 + j];
    const float bi = g_bin[j], bh = g_bhn[j];
    const float wqj = wq[j], bqj = bq[j];
    const int offx = blockIdx.x & 31;
    const int offh = (blockIdx.x * 37) & 127;
    __syncthreads();

    int q = offx;
    float4 wa = g_W6a[q * 256 + j];
    float2 wb = g_W6b[q * 256 + j];

    for (int t = 0; t < TT; t++) {
        // prefetch x_{t+1} (1024 elements / 512 threads)
        float xr[2];
#pragma unroll
        for (int r = 0; r < 2; r++) {
            int i = tid + 512 * r;
            int b = i >> 6, k = i & 63;
            xr[r] = (t + 1 < TT) ? x[((size_t)(B0 + b) * TT + (t + 1)) * FF + k] : 0.f;
        }

        u64 aR[4], aZ[4], aI[4], aH[4];
#pragma unroll
        for (int p = 0; p < 4; p++) { aR[p] = 0; aZ[p] = 0; aI[p] = 0; aH[p] = 0; }

        for (int i = 0; i < 32; i++) {               // x-part (k<64): r,z,i_n
            int qn = (i == 31) ? (32 + offh) : ((offx + i + 1) & 31);
            float4 wan = g_W6a[qn * 256 + j];
            float2 wbn = g_W6b[qn * 256 + j];
            ENC_BODY(2 * q, aI);
            wa = wan; wb = wbn; q = qn;
        }
        for (int i = 0; i < 128; i++) {              // h-part (k>=64): r,z,h_n
            int qn = (i == 127) ? offx : (32 + ((offh + i + 1) & 127));
            float4 wan = g_W6a[qn * 256 + j];
            float2 wbn = g_W6b[qn * 256 + j];
            ENC_BODY(2 * q, aH);
            wa = wan; wb = wbn; q = qn;
        }
        __syncthreads();   // all GEMM reads of As done

        // GRU elementwise in-register for this thread's 4 pairs; h update; fp16 hs; A/C
        __half* __restrict__ hsh = g_hsh + ((size_t)t * BB + B0) * HH + j;
#pragma unroll
        for (int pp = 0; pp < 4; pp++) {
            const int p = half * 4 + pp;
            float2 fr = u2f(aR[pp]), fz = u2f(aZ[pp]), fi = u2f(aI[pp]), fh = u2f(aH[pp]);
            float2 hp = As[(64 + j) * ASP + p];
            float r0 = sigf(fr.x + brz1), z0 = sigf(fz.x + brz2);
            float n0 = tanhf(fi.x + bi + r0 * (fh.x + bh));
            float h0n = (1.f - z0) * n0 + z0 * hp.x;
            float r1 = sigf(fr.y + brz1), z1 = sigf(fz.y + brz2);
            float n1 = tanhf(fi.y + bi + r1 * (fh.y + bh));
            float h1n = (1.f - z1) * n1 + z1 * hp.y;
            As[(64 + j) * ASP + p] = make_float2(h0n, h1n);
            hsh[(size_t)(2 * p) * HH]     = __float2half_rn(h0n);
            hsh[(size_t)(2 * p + 1) * HH] = __float2half_rn(h1n);
            float2 pa = make_float2(wqj * h0n, wqj * h1n);
            float2 pc = make_float2(bqj * h0n, bqj * h1n);
#pragma unroll
            for (int o = 16; o > 0; o >>= 1) {
                pa.x += __shfl_xor_sync(0xffffffffu, pa.x, o);
                pa.y += __shfl_xor_sync(0xffffffffu, pa.y, o);
                pc.x += __shfl_xor_sync(0xffffffffu, pc.x, o);
                pc.y += __shfl_xor_sync(0xffffffffu, pc.y, o);
            }
            if (lane == 0) { redA[wid * 4 + pp] = pa; redC[wid * 4 + pp] = pc; }
        }
        // store x_{t+1}
#pragma unroll
        for (int r = 0; r < 2; r++) {
            int i = tid + 512 * r;
            int b = i >> 6, k = i & 63;
            Asf[(k * ASP + (b >> 1)) * 2 + (b & 1)] = xr[r];
        }
        __syncthreads();   // As + redA/redC ready

        if (tid < 8) {     // finalize A/C: pair p reduced over the 8 warps of its half
            const int hp8 = (tid >> 2) * 8, pl = tid & 3;
            float2 A = make_float2(0.f, 0.f), C = make_float2(0.f, 0.f);
#pragma unroll
            for (int w = 0; w < 8; w++) {
                float2 a = redA[(hp8 + w) * 4 + pl], c = redC[(hp8 + w) * 4 + pl];
                A.x += a.x; A.y += a.y; C.x += c.x; C.y += c.y;
            }
            g_Abt[(size_t)(B0 + 2 * tid) * TT + t]     = A.x * 0.0625f;
            g_Abt[(size_t)(B0 + 2 * tid + 1) * TT + t] = A.y * 0.0625f;
            g_Cbt[(size_t)(B0 + 2 * tid) * TT + t]     = C.x * 0.0625f;
            g_Cbt[(size_t)(B0 + 2 * tid + 1) * TT + t] = C.y * 0.0625f;
        }
    }
}

#define DEC_STEP6(K0) do {                                                                 \
    const double2* _av0 = reinterpret_cast<const double2*>(ctxp + (K0) * 8);               \
    const double2* _av1 = reinterpret_cast<const double2*>(ctxp + ((K0) + 1) * 8);         \
    u64 _p00 = pack2(wa.x), _p01 = pack2(wa.y), _p02 = pack2(wa.z);                        \
    u64 _p10 = pack2(wa.w), _p11 = pack2(wb.x), _p12 = pack2(wb.y);                        \
    _Pragma("unroll")                                                                      \
    for (int _h = 0; _h < 4; _h++) {                                                       \
        double2 _d0 = _av0[_h], _d1 = _av1[_h];                                            \
        u64 _a00 = __double_as_longlong(_d0.x), _a01 = __double_as_longlong(_d0.y);        \
        u64 _a10 = __double_as_longlong(_d1.x), _a11 = __double_as_longlong(_d1.y);        \
        fma2(ar[2*_h],   _p00, _a00); fma2(az[2*_h],   _p01, _a00); fma2(an[2*_h],   _p02, _a00); \
        fma2(ar[2*_h+1], _p00, _a01); fma2(az[2*_h+1], _p01, _a01); fma2(an[2*_h+1], _p02, _a01); \
        fma2(ar[2*_h],   _p10, _a10); fma2(az[2*_h],   _p11, _a10); fma2(an[2*_h],   _p12, _a10); \
        fma2(ar[2*_h+1], _p10, _a11); fma2(az[2*_h+1], _p11, _a11); fma2(an[2*_h+1], _p12, _a11); \
    }                                                                                      \
} while (0)

// ---- persistent decoder: all 32 steps fused (R6 proven version) ----
__global__ void __launch_bounds__(256) dec_all_kernel(const float* __restrict__ dWih,
                                                      const float* __restrict__ fc1b,
                                                      const float* __restrict__ fc2W,
                                                      const float* __restrict__ fc2b,
                                                      float* __restrict__ out) {
    __shared__ char smraw[8192 + 16384 + 16384 + 64];
    float*  s     = reinterpret_cast<float*>(smraw);                 // [16][128]
    float2* ctxp  = reinterpret_cast<float2*>(smraw + 8192);         // [256][8] pairs
    float*  f1s   = reinterpret_cast<float*>(smraw + 8192);          // overlays ctxp
    float2* hdp   = reinterpret_cast<float2*>(smraw + 8192 + 16384); // [256][8] pairs
    float*  prevs = reinterpret_cast<float*>(smraw + 8192 + 32768);  // [16]
    const int tid = threadIdx.x;
    const int B0 = blockIdx.x * BM;
    const int wid = tid >> 5, lane = tid & 31;
    const int j = tid;
    const int toff = (blockIdx.x * 29) & 127;
    const int qoff = (blockIdx.x * 13) & 127;

    if (tid < BM) prevs[tid] = g_prev[B0 + tid];
    const float dwr = dWih[j], dwz = dWih[256 + j], dwn = dWih[512 + j];
    const float br = g_dbrz[j], bz = g_dbrz[256 + j], bi = g_dbin[j], bh = g_dbhn[j];
    const float b1 = fc1b[tid], fb = fc2b[0];
    float w2r[8];
#pragma unroll
    for (int qq = 0; qq < 8; qq++) w2r[qq] = fc2W[lane + 32 * qq];
    __syncthreads();

    for (int step = 0; step < OL; step++) {
        for (int i = tid; i < BM * TT; i += 256) {
            int b = i >> 7;
            s[i] = prevs[b] * g_Abt[(size_t)B0 * TT + i] + g_Cbt[(size_t)B0 * TT + i];
        }
        __syncthreads();

#pragma unroll
        for (int bb = 0; bb < 2; bb++) {
            int b = wid * 2 + bb;
            float v0 = s[b*TT+lane], v1 = s[b*TT+lane+32], v2 = s[b*TT+lane+64], v3 = s[b*TT+lane+96];
            float m = fmaxf(fmaxf(v0, v1), fmaxf(v2, v3));
#pragma unroll
            for (int o = 16; o > 0; o >>= 1) m = fmaxf(m, __shfl_xor_sync(0xffffffffu, m, o));
            float e0 = __expf(v0-m), e1 = __expf(v1-m), e2 = __expf(v2-m), e3 = __expf(v3-m);
            float sum = e0 + e1 + e2 + e3;
#pragma unroll
            for (int o = 16; o > 0; o >>= 1) sum += __shfl_xor_sync(0xffffffffu, sum, o);
            float inv = 1.f / sum;
            s[b*TT+lane] = e0*inv; s[b*TT+lane+32] = e1*inv; s[b*TT+lane+64] = e2*inv; s[b*TT+lane+96] = e3*inv;
        }
        __syncthreads();

        {   // ctx[b][j] = sum_t w[b,t] * hs_fp16[t][b][j], fp32 packed accumulate
            const int jv = (tid & 63) * 4;
            const int bs = tid >> 6;
            u64 c0[2] = {0,0}, c1[2] = {0,0}, c2[2] = {0,0}, c3[2] = {0,0};
#pragma unroll 4
            for (int i = 0; i < TT; i++) {
                int t = (i + toff) & 127;
                const uint2* hb = reinterpret_cast<const uint2*>(
                    g_hsh + ((size_t)t * BB + B0) * HH) + (jv >> 2);
                float w0 = s[(bs+0)*TT+t], w1 = s[(bs+4)*TT+t], w2 = s[(bs+8)*TT+t], w3 = s[(bs+12)*TT+t];
                uint2 v0 = hb[(bs+0)*64], v1 = hb[(bs+4)*64], v2 = hb[(bs+8)*64], v3 = hb[(bs+12)*64];
                u64 wp0 = pack2(w0), wp1 = pack2(w1), wp2 = pack2(w2), wp3 = pack2(w3);
                fma2(c0[0], wp0, hfp(v0.x)); fma2(c0[1], wp0, hfp(v0.y));
                fma2(c1[0], wp1, hfp(v1.x)); fma2(c1[1], wp1, hfp(v1.y));
                fma2(c2[0], wp2, hfp(v2.x)); fma2(c2[1], wp2, hfp(v2.y));
                fma2(c3[0], wp3, hfp(v3.x)); fma2(c3[1], wp3, hfp(v3.y));
            }
            float* cf = reinterpret_cast<float*>(ctxp);
            u64* cc[4] = {c0, c1, c2, c3};
#pragma unroll
            for (int qq = 0; qq < 4; qq++) {
                int b = bs + 4 * qq, p = b >> 1, par = b & 1;
                float2 lo = u2f(cc[qq][0]), hi = u2f(cc[qq][1]);
                cf[((jv+0)*8+p)*2+par] = lo.x; cf[((jv+1)*8+p)*2+par] = lo.y;
                cf[((jv+2)*8+p)*2+par] = hi.x; cf[((jv+3)*8+p)*2+par] = hi.y;
            }
        }
        __syncthreads();

        u64 ar[8], az[8], an[8];
#pragma unroll
        for (int p = 0; p < 8; p++) { ar[p] = 0; az[p] = 0; an[p] = 0; }
        {   // gh = ctx @ dec_Whh^T (staggered, prefetch depth 1)
            int q = qoff;
            float4 wa = g_D6a[q * 256 + tid];
            float2 wb = g_D6b[q * 256 + tid];
            for (int i = 0; i < 128; i++) {
                int qn = (qoff + i + 1) & 127;
                float4 wan = g_D6a[qn * 256 + tid];
                float2 wbn = g_D6b[qn * 256 + tid];
                DEC_STEP6(2 * q);
                wa = wan; wb = wbn; q = qn;
            }
        }
        {   // decoder GRU elementwise (x = prev scalar, h = ctx)
#pragma unroll
            for (int p = 0; p < 8; p++) {
                float2 fr = u2f(ar[p]), fz = u2f(az[p]), fn = u2f(an[p]);
                float2 cx = ctxp[j * 8 + p];
                float2 hd;
                float pv = prevs[2 * p];
                float r = sigf(pv * dwr + fr.x + br);
                float z = sigf(pv * dwz + fz.x + bz);
                float n = tanhf(pv * dwn + bi + r * (fn.x + bh));
                hd.x = (1.f - z) * n + z * cx.x;
                pv = prevs[2 * p + 1];
                r = sigf(pv * dwr + fr.y + br);
                z = sigf(pv * dwz + fz.y + bz);
                n = tanhf(pv * dwn + bi + r * (fn.y + bh));
                hd.y = (1.f - z) * n + z * cx.y;
                hdp[j * 8 + p] = hd;
            }
        }
        __syncthreads();   // hdp ready; ctxp reusable as f1s

        {   // fc1 + relu (staggered, prefetch depth 1)
            u64 f[8];
#pragma unroll
            for (int p = 0; p < 8; p++) f[p] = 0;
            int q = qoff;
            float2 wf = g_F2[q * 256 + tid];
            for (int i = 0; i < 128; i++) {
                int qn = (qoff + i + 1) & 127;
                float2 wfn = g_F2[qn * 256 + tid];
                const double2* hv0 = reinterpret_cast<const double2*>(hdp + (2 * q) * 8);
                const double2* hv1 = reinterpret_cast<const double2*>(hdp + (2 * q + 1) * 8);
                u64 w0 = pack2(wf.x), w1 = pack2(wf.y);
#pragma unroll
                for (int h = 0; h < 4; h++) {
                    double2 d0 = hv0[h], d1 = hv1[h];
                    fma2(f[2*h],   w0, __double_as_longlong(d0.x));
                    fma2(f[2*h+1], w0, __double_as_longlong(d0.y));
                    fma2(f[2*h],   w1, __double_as_longlong(d1.x));
                    fma2(f[2*h+1], w1, __double_as_longlong(d1.y));
                }
                wf = wfn; q = qn;
            }
#pragma unroll
            for (int p = 0; p < 8; p++) {
                float2 v = u2f(f[p]);
                f1s[(2*p)*FCH + tid]   = fmaxf(v.x + b1, 0.f);
                f1s[(2*p+1)*FCH + tid] = fmaxf(v.y + b1, 0.f);
            }
        }
        __syncthreads();

        {   // fc2: warp reduces 2 batches; carry prev in smem
#pragma unroll
            for (int bb = 0; bb < 2; bb++) {
                int b = wid * 2 + bb;
                float a = 0.f;
#pragma unroll
                for (int qq = 0; qq < 8; qq++)
                    a += f1s[b * FCH + lane + 32 * qq] * w2r[qq];
#pragma unroll
                for (int o = 16; o > 0; o >>= 1) a += __shfl_xor_sync(0xffffffffu, a, o);
                if (lane == 0) {
                    float v = a + fb;
                    out[(size_t)(B0 + b) * OL + step] = v;
                    prevs[b] = v;
                }
            }
        }
        __syncthreads();
    }
}

extern "C" void kernel_launch(void* const* d_in, const int* in_sizes, int n_in,
                              void* d_out, int out_size) {
    const float* x      = (const float*)d_in[0];
    const float* h      = (const float*)d_in[1];
    const float* eWih   = (const float*)d_in[2];
    const float* eWhh   = (const float*)d_in[3];
    const float* ebih   = (const float*)d_in[4];
    const float* ebhh   = (const float*)d_in[5];
    const float* dWih   = (const float*)d_in[6];
    const float* dWhh   = (const float*)d_in[7];
    const float* dbih   = (const float*)d_in[8];
    const float* dbhh   = (const float*)d_in[9];
    const float* wq     = (const float*)d_in[10];
    const float* bq     = (const float*)d_in[11];
    const float* fc1W   = (const float*)d_in[12];
    const float* fc1b   = (const float*)d_in[13];
    const float* fc2W   = (const float*)d_in[14];
    const float* fc2b   = (const float*)d_in[15];
    float* out = (float*)d_out;

    prep_kernel<<<256, 256>>>(x, eWih, eWhh, ebih, ebhh, dWhh, dbih, dbhh, fc1W);
    enc_all_kernel<<<BB / BM, 512>>>(x, h, wq, bq);
    dec_all_kernel<<<BB / BM, 256>>>(dWih, fc1b, fc2W, fc2b, out);
}

// round 12
// speedup vs baseline: 1.5875x; 1.5875x over previous
#include <cuda_runtime.h>
#include <cuda_fp16.h>
#include <cstdint>
#include <cstddef>

#define BB   2048
#define TT   128
#define FF   64
#define HH   256
#define G3   768
#define OL   32
#define FCH  256
#define BM   16
#define ASP  10          // float2 pairs per As row (8 used + 2 pad -> 80B rows, 16B aligned)

// ---- device scratch ----
__device__ __half g_hsh[(size_t)TT * BB * HH];          // [t][b][j] fp16 (ctx source)
__device__ uint2    g_W4h[160 * 256];                   // enc packed fp16 weights (4 of 6)
__device__ unsigned g_W2h[160 * 256];                   // enc packed fp16 weights (2 of 6)
__device__ float4 g_D6a[128 * 256];                     // dec_Whh packed (fp32)
__device__ float2 g_D6b[128 * 256];
__device__ float2 g_F2 [128 * 256];                     // fc1 packed (fp32)
__device__ float  g_brz[512], g_bin[256], g_bhn[256];
__device__ float  g_dbrz[512], g_dbin[256], g_dbhn[256];
__device__ float  g_Abt[(size_t)BB * TT];
__device__ float  g_Cbt[(size_t)BB * TT];
__device__ float  g_prev[BB];

typedef unsigned long long u64;

__device__ __forceinline__ void fma2(u64 &d, u64 a, u64 b) {
    asm("fma.rn.f32x2 %0, %1, %2, %0;" : "+l"(d) : "l"(a), "l"(b));
}
__device__ __forceinline__ u64 pack2(float w) {
    u64 r; unsigned int u = __float_as_uint(w);
    asm("mov.b64 %0, {%1,%1};" : "=l"(r) : "r"(u));
    return r;
}
__device__ __forceinline__ float2 u2f(u64 v) {
    float2 r;
    asm("mov.b64 {%0, %1}, %2;" : "=f"(r.x), "=f"(r.y) : "l"(v));
    return r;
}
// two fp16 (packed in u32) -> packed f32x2 (exact widening)
__device__ __forceinline__ u64 hfp(unsigned v) {
    __half2 h2 = *reinterpret_cast<__half2*>(&v);
    float2 f = __half22float2(h2);
    u64 r;
    asm("mov.b64 %0, {%1,%2};" : "=l"(r) : "f"(f.x), "f"(f.y));
    return r;
}
__device__ __forceinline__ float2 h2f(unsigned v) {
    __half2 h2 = *reinterpret_cast<__half2*>(&v);
    return __half22float2(h2);
}
__device__ __forceinline__ unsigned f2h2(float a, float b) {
    __half2 h = __floats2half2_rn(a, b);
    return *reinterpret_cast<unsigned*>(&h);
}
__device__ __forceinline__ float sigf(float x) { return 1.f / (1.f + __expf(-x)); }

// ---- prep: packed weight streams + bias folding + prev0 ----
__global__ void prep_kernel(const float* __restrict__ x,
                            const float* __restrict__ eWih, const float* __restrict__ eWhh,
                            const float* __restrict__ ebih, const float* __restrict__ ebhh,
                            const float* __restrict__ dWhh,
                            const float* __restrict__ dbih, const float* __restrict__ dbhh,
                            const float* __restrict__ fc1W) {
    const int stride = gridDim.x * blockDim.x;
    const int id = blockIdx.x * blockDim.x + threadIdx.x;
    // encoder pack: thread j owns gate rows j (r), 256+j (z), 512+j (i_n / h_n); fp16 storage
    for (int i = id; i < 160 * 256; i += stride) {
        int q = i >> 8, j = i & 255;
        float wr0, wz0, w30, wr1, wz1, w31;
        if (q < 32) {
            int k0 = 2 * q, k1 = k0 + 1;
            wr0 = eWih[j * 64 + k0];         wr1 = eWih[j * 64 + k1];
            wz0 = eWih[(256 + j) * 64 + k0]; wz1 = eWih[(256 + j) * 64 + k1];
            w30 = eWih[(512 + j) * 64 + k0]; w31 = eWih[(512 + j) * 64 + k1];
        } else {
            int k0 = 2 * q - 64, k1 = k0 + 1;
            wr0 = eWhh[j * 256 + k0];         wr1 = eWhh[j * 256 + k1];
            wz0 = eWhh[(256 + j) * 256 + k0]; wz1 = eWhh[(256 + j) * 256 + k1];
            w30 = eWhh[(512 + j) * 256 + k0]; w31 = eWhh[(512 + j) * 256 + k1];
        }
        g_W4h[i] = make_uint2(f2h2(wr0, wz0), f2h2(w30, wr1));
        g_W2h[i] = f2h2(wz1, w31);
    }
    for (int i = id; i < 128 * 256; i += stride) {
        int q = i >> 8, j = i & 255;
        int k0 = 2 * q, k1 = k0 + 1;
        g_D6a[i] = make_float4(dWhh[j * 256 + k0], dWhh[(256 + j) * 256 + k0],
                               dWhh[(512 + j) * 256 + k0], dWhh[j * 256 + k1]);
        g_D6b[i] = make_float2(dWhh[(256 + j) * 256 + k1], dWhh[(512 + j) * 256 + k1]);
        g_F2[i]  = make_float2(fc1W[j * 256 + k0], fc1W[j * 256 + k1]);
    }
    for (int i = id; i < 512; i += stride) {
        g_brz[i]  = ebih[i] + ebhh[i];
        g_dbrz[i] = dbih[i] + dbhh[i];
    }
    for (int i = id; i < 256; i += stride) {
        g_bin[i]  = ebih[512 + i];  g_bhn[i]  = ebhh[512 + i];
        g_dbin[i] = dbih[512 + i];  g_dbhn[i] = dbhh[512 + i];
    }
    for (int i = id; i < BB; i += stride)
        g_prev[i] = x[((size_t)i * TT + (TT - 1)) * FF];
}

// 2-k FMA body: wa (uint2: 4 fp16), wb (unsigned: 2 fp16); AS = third accumulator set
#define ENC_STEP6(K0, AS) do {                                                             \
    const double2* _av0 = reinterpret_cast<const double2*>(As + (K0) * ASP);               \
    const double2* _av1 = reinterpret_cast<const double2*>(As + ((K0) + 1) * ASP);         \
    float2 _f0 = h2f(wa.x), _f1 = h2f(wa.y), _f2 = h2f(wb);                                \
    u64 _p00 = pack2(_f0.x), _p01 = pack2(_f0.y), _p02 = pack2(_f1.x);                     \
    u64 _p10 = pack2(_f1.y), _p11 = pack2(_f2.x), _p12 = pack2(_f2.y);                     \
    _Pragma("unroll")                                                                      \
    for (int _h = 0; _h < 4; _h++) {                                                       \
        double2 _d0 = _av0[_h], _d1 = _av1[_h];                                            \
        u64 _a00 = __double_as_longlong(_d0.x), _a01 = __double_as_longlong(_d0.y);        \
        u64 _a10 = __double_as_longlong(_d1.x), _a11 = __double_as_longlong(_d1.y);        \
        fma2(aR[2*_h],   _p00, _a00); fma2(aZ[2*_h],   _p01, _a00); fma2(AS[2*_h],   _p02, _a00); \
        fma2(aR[2*_h+1], _p00, _a01); fma2(aZ[2*_h+1], _p01, _a01); fma2(AS[2*_h+1], _p02, _a01); \
        fma2(aR[2*_h],   _p10, _a10); fma2(aZ[2*_h],   _p11, _a10); fma2(AS[2*_h],   _p12, _a10); \
        fma2(aR[2*_h+1], _p10, _a11); fma2(aZ[2*_h+1], _p11, _a11); fma2(AS[2*_h+1], _p12, _a11); \
    }                                                                                      \
} while (0)

// ---- persistent encoder: 256 threads, h in smem, gates in registers,
//      fp16 weight stream (half L2 traffic), exact A/C in-kernel ----
__global__ void __launch_bounds__(256) enc_all_kernel(const float* __restrict__ x,
                                                      const float* __restrict__ h0,
                                                      const float* __restrict__ wq,
                                                      const float* __restrict__ bq) {
    __shared__ float2 As[320 * ASP];            // x rows 0..63, h rows 64..319
    __shared__ float2 redA[8 * 8], redC[8 * 8]; // [warp][pair]
    float* Asf = reinterpret_cast<float*>(As);
    const int tid = threadIdx.x;
    const int B0 = blockIdx.x * BM;
    const int wid = tid >> 5, lane = tid & 31;

    for (int i = tid; i < BM * HH; i += 256) {
        int b = i >> 8, k = i & 255;
        Asf[((64 + k) * ASP + (b >> 1)) * 2 + (b & 1)] = h0[(size_t)(B0 + b) * HH + k];
    }
    for (int i = tid; i < BM * FF; i += 256) {
        int b = i >> 6, k = i & 63;
        Asf[(k * ASP + (b >> 1)) * 2 + (b & 1)] = x[((size_t)(B0 + b) * TT + 0) * FF + k];
    }
    const float brz1 = g_brz[tid], brz2 = g_brz[256 + tid];
    const float bi = g_bin[tid], bh = g_bhn[tid];
    const float wqj = wq[tid], bqj = bq[tid];
    const int offx = blockIdx.x & 31;
    const int offh = (blockIdx.x * 37) & 127;
    __syncthreads();

    int q = offx;
    uint2    wa = g_W4h[q * 256 + tid];
    unsigned wb = g_W2h[q * 256 + tid];

    for (int t = 0; t < TT; t++) {
        // prefetch x_{t+1}
        float xr[4];
#pragma unroll
        for (int r = 0; r < 4; r++) {
            int i = tid + 256 * r;
            int b = i >> 6, k = i & 63;
            xr[r] = (t + 1 < TT) ? x[((size_t)(B0 + b) * TT + (t + 1)) * FF + k] : 0.f;
        }

        u64 aR[8], aZ[8], aI[8], aH[8];
#pragma unroll
        for (int p = 0; p < 8; p++) { aR[p] = 0; aZ[p] = 0; aI[p] = 0; aH[p] = 0; }

        for (int i = 0; i < 32; i++) {               // x-part (k<64): r,z,i_n
            int qn = (i == 31) ? (32 + offh) : ((offx + i + 1) & 31);
            uint2    wan = g_W4h[qn * 256 + tid];
            unsigned wbn = g_W2h[qn * 256 + tid];
            ENC_STEP6(2 * q, aI);
            wa = wan; wb = wbn; q = qn;
        }
        for (int i = 0; i < 128; i++) {              // h-part (k>=64): r,z,h_n
            int qn = (i == 127) ? offx : (32 + ((offh + i + 1) & 127));
            uint2    wan = g_W4h[qn * 256 + tid];
            unsigned wbn = g_W2h[qn * 256 + tid];
            ENC_STEP6(2 * q, aH);
            wa = wan; wb = wbn; q = qn;
        }
        __syncthreads();   // all GEMM reads of As done

        // GRU elementwise in-register; h update in smem; fp16 hs store; A/C partials
        __half* __restrict__ hsh = g_hsh + ((size_t)t * BB + B0) * HH + tid;
#pragma unroll
        for (int p = 0; p < 8; p++) {
            float2 fr = u2f(aR[p]), fz = u2f(aZ[p]), fi = u2f(aI[p]), fh = u2f(aH[p]);
            float2 hp = As[(64 + tid) * ASP + p];
            float r0 = sigf(fr.x + brz1), z0 = sigf(fz.x + brz2);
            float n0 = tanhf(fi.x + bi + r0 * (fh.x + bh));
            float h0n = (1.f - z0) * n0 + z0 * hp.x;
            float r1 = sigf(fr.y + brz1), z1 = sigf(fz.y + brz2);
            float n1 = tanhf(fi.y + bi + r1 * (fh.y + bh));
            float h1n = (1.f - z1) * n1 + z1 * hp.y;
            As[(64 + tid) * ASP + p] = make_float2(h0n, h1n);
            hsh[(size_t)(2 * p) * HH]     = __float2half_rn(h0n);
            hsh[(size_t)(2 * p + 1) * HH] = __float2half_rn(h1n);
            float2 pa = make_float2(wqj * h0n, wqj * h1n);
            float2 pc = make_float2(bqj * h0n, bqj * h1n);
#pragma unroll
            for (int o = 16; o > 0; o >>= 1) {
                pa.x += __shfl_xor_sync(0xffffffffu, pa.x, o);
                pa.y += __shfl_xor_sync(0xffffffffu, pa.y, o);
                pc.x += __shfl_xor_sync(0xffffffffu, pc.x, o);
                pc.y += __shfl_xor_sync(0xffffffffu, pc.y, o);
            }
            if (lane == 0) { redA[wid * 8 + p] = pa; redC[wid * 8 + p] = pc; }
        }
        // store x_{t+1}
#pragma unroll
        for (int r = 0; r < 4; r++) {
            int i = tid + 256 * r;
            int b = i >> 6, k = i & 63;
            Asf[(k * ASP + (b >> 1)) * 2 + (b & 1)] = xr[r];
        }
        __syncthreads();   // As + redA/redC ready

        if (tid < 8) {     // finalize A/C for this block's 16 batches
            float2 A = make_float2(0.f, 0.f), C = make_float2(0.f, 0.f);
#pragma unroll
            for (int w = 0; w < 8; w++) {
                float2 a = redA[w * 8 + tid], c = redC[w * 8 + tid];
                A.x += a.x; A.y += a.y; C.x += c.x; C.y += c.y;
            }
            g_Abt[(size_t)(B0 + 2 * tid) * TT + t]     = A.x * 0.0625f;
            g_Abt[(size_t)(B0 + 2 * tid + 1) * TT + t] = A.y * 0.0625f;
            g_Cbt[(size_t)(B0 + 2 * tid) * TT + t]     = C.x * 0.0625f;
            g_Cbt[(size_t)(B0 + 2 * tid + 1) * TT + t] = C.y * 0.0625f;
        }
    }
}

#define DEC_STEP6(K0) do {                                                                 \
    const double2* _av0 = reinterpret_cast<const double2*>(ctxp + (K0) * 8);               \
    const double2* _av1 = reinterpret_cast<const double2*>(ctxp + ((K0) + 1) * 8);         \
    u64 _p00 = pack2(wa.x), _p01 = pack2(wa.y), _p02 = pack2(wa.z);                        \
    u64 _p10 = pack2(wa.w), _p11 = pack2(wb.x), _p12 = pack2(wb.y);                        \
    _Pragma("unroll")                                                                      \
    for (int _h = 0; _h < 4; _h++) {                                                       \
        double2 _d0 = _av0[_h], _d1 = _av1[_h];                                            \
        u64 _a00 = __double_as_longlong(_d0.x), _a01 = __double_as_longlong(_d0.y);        \
        u64 _a10 = __double_as_longlong(_d1.x), _a11 = __double_as_longlong(_d1.y);        \
        fma2(ar[2*_h],   _p00, _a00); fma2(az[2*_h],   _p01, _a00); fma2(an[2*_h],   _p02, _a00); \
        fma2(ar[2*_h+1], _p00, _a01); fma2(az[2*_h+1], _p01, _a01); fma2(an[2*_h+1], _p02, _a01); \
        fma2(ar[2*_h],   _p10, _a10); fma2(az[2*_h],   _p11, _a10); fma2(an[2*_h],   _p12, _a10); \
        fma2(ar[2*_h+1], _p10, _a11); fma2(az[2*_h+1], _p11, _a11); fma2(an[2*_h+1], _p12, _a11); \
    }                                                                                      \
} while (0)

// ---- persistent decoder: all 32 steps fused (R6 proven version, fp32 weights) ----
__global__ void __launch_bounds__(256) dec_all_kernel(const float* __restrict__ dWih,
                                                      const float* __restrict__ fc1b,
                                                      const float* __restrict__ fc2W,
                                                      const float* __restrict__ fc2b,
                                                      float* __restrict__ out) {
    __shared__ char smraw[8192 + 16384 + 16384 + 64];
    float*  s     = reinterpret_cast<float*>(smraw);                 // [16][128]
    float2* ctxp  = reinterpret_cast<float2*>(smraw + 8192);         // [256][8] pairs
    float*  f1s   = reinterpret_cast<float*>(smraw + 8192);          // overlays ctxp
    float2* hdp   = reinterpret_cast<float2*>(smraw + 8192 + 16384); // [256][8] pairs
    float*  prevs = reinterpret_cast<float*>(smraw + 8192 + 32768);  // [16]
    const int tid = threadIdx.x;
    const int B0 = blockIdx.x * BM;
    const int wid = tid >> 5, lane = tid & 31;
    const int j = tid;
    const int toff = (blockIdx.x * 29) & 127;
    const int qoff = (blockIdx.x * 13) & 127;

    if (tid < BM) prevs[tid] = g_prev[B0 + tid];
    const float dwr = dWih[j], dwz = dWih[256 + j], dwn = dWih[512 + j];
    const float br = g_dbrz[j], bz = g_dbrz[256 + j], bi = g_dbin[j], bh = g_dbhn[j];
    const float b1 = fc1b[tid], fb = fc2b[0];
    float w2r[8];
#pragma unroll
    for (int qq = 0; qq < 8; qq++) w2r[qq] = fc2W[lane + 32 * qq];
    __syncthreads();

    for (int step = 0; step < OL; step++) {
        for (int i = tid; i < BM * TT; i += 256) {
            int b = i >> 7;
            s[i] = prevs[b] * g_Abt[(size_t)B0 * TT + i] + g_Cbt[(size_t)B0 * TT + i];
        }
        __syncthreads();

#pragma unroll
        for (int bb = 0; bb < 2; bb++) {
            int b = wid * 2 + bb;
            float v0 = s[b*TT+lane], v1 = s[b*TT+lane+32], v2 = s[b*TT+lane+64], v3 = s[b*TT+lane+96];
            float m = fmaxf(fmaxf(v0, v1), fmaxf(v2, v3));
#pragma unroll
            for (int o = 16; o > 0; o >>= 1) m = fmaxf(m, __shfl_xor_sync(0xffffffffu, m, o));
            float e0 = __expf(v0-m), e1 = __expf(v1-m), e2 = __expf(v2-m), e3 = __expf(v3-m);
            float sum = e0 + e1 + e2 + e3;
#pragma unroll
            for (int o = 16; o > 0; o >>= 1) sum += __shfl_xor_sync(0xffffffffu, sum, o);
            float inv = 1.f / sum;
            s[b*TT+lane] = e0*inv; s[b*TT+lane+32] = e1*inv; s[b*TT+lane+64] = e2*inv; s[b*TT+lane+96] = e3*inv;
        }
        __syncthreads();

        {   // ctx[b][j] = sum_t w[b,t] * hs_fp16[t][b][j], fp32 packed accumulate
            const int jv = (tid & 63) * 4;
            const int bs = tid >> 6;
            u64 c0[2] = {0,0}, c1[2] = {0,0}, c2[2] = {0,0}, c3[2] = {0,0};
#pragma unroll 4
            for (int i = 0; i < TT; i++) {
                int t = (i + toff) & 127;
                const uint2* hb = reinterpret_cast<const uint2*>(
                    g_hsh + ((size_t)t * BB + B0) * HH) + (jv >> 2);
                float w0 = s[(bs+0)*TT+t], w1 = s[(bs+4)*TT+t], w2 = s[(bs+8)*TT+t], w3 = s[(bs+12)*TT+t];
                uint2 v0 = hb[(bs+0)*64], v1 = hb[(bs+4)*64], v2 = hb[(bs+8)*64], v3 = hb[(bs+12)*64];
                u64 wp0 = pack2(w0), wp1 = pack2(w1), wp2 = pack2(w2), wp3 = pack2(w3);
                fma2(c0[0], wp0, hfp(v0.x)); fma2(c0[1], wp0, hfp(v0.y));
                fma2(c1[0], wp1, hfp(v1.x)); fma2(c1[1], wp1, hfp(v1.y));
                fma2(c2[0], wp2, hfp(v2.x)); fma2(c2[1], wp2, hfp(v2.y));
                fma2(c3[0], wp3, hfp(v3.x)); fma2(c3[1], wp3, hfp(v3.y));
            }
            float* cf = reinterpret_cast<float*>(ctxp);
            u64* cc[4] = {c0, c1, c2, c3};
#pragma unroll
            for (int qq = 0; qq < 4; qq++) {
                int b = bs + 4 * qq, p = b >> 1, par = b & 1;
                float2 lo = u2f(cc[qq][0]), hi = u2f(cc[qq][1]);
                cf[((jv+0)*8+p)*2+par] = lo.x; cf[((jv+1)*8+p)*2+par] = lo.y;
                cf[((jv+2)*8+p)*2+par] = hi.x; cf[((jv+3)*8+p)*2+par] = hi.y;
            }
        }
        __syncthreads();

        u64 ar[8], az[8], an[8];
#pragma unroll
        for (int p = 0; p < 8; p++) { ar[p] = 0; az[p] = 0; an[p] = 0; }
        {   // gh = ctx @ dec_Whh^T (staggered, prefetch depth 1)
            int q = qoff;
            float4 wa = g_D6a[q * 256 + tid];
            float2 wb = g_D6b[q * 256 + tid];
            for (int i = 0; i < 128; i++) {
                int qn = (qoff + i + 1) & 127;
                float4 wan = g_D6a[qn * 256 + tid];
                float2 wbn = g_D6b[qn * 256 + tid];
                DEC_STEP6(2 * q);
                wa = wan; wb = wbn; q = qn;
            }
        }
        {   // decoder GRU elementwise (x = prev scalar, h = ctx)
#pragma unroll
            for (int p = 0; p < 8; p++) {
                float2 fr = u2f(ar[p]), fz = u2f(az[p]), fn = u2f(an[p]);
                float2 cx = ctxp[j * 8 + p];
                float2 hd;
                float pv = prevs[2 * p];
                float r = sigf(pv * dwr + fr.x + br);
                float z = sigf(pv * dwz + fz.x + bz);
                float n = tanhf(pv * dwn + bi + r * (fn.x + bh));
                hd.x = (1.f - z) * n + z * cx.x;
                pv = prevs[2 * p + 1];
                r = sigf(pv * dwr + fr.y + br);
                z = sigf(pv * dwz + fz.y + bz);
                n = tanhf(pv * dwn + bi + r * (fn.y + bh));
                hd.y = (1.f - z) * n + z * cx.y;
                hdp[j * 8 + p] = hd;
            }
        }
        __syncthreads();   // hdp ready; ctxp reusable as f1s

        {   // fc1 + relu (staggered, prefetch depth 1)
            u64 f[8];
#pragma unroll
            for (int p = 0; p < 8; p++) f[p] = 0;
            int q = qoff;
            float2 wf = g_F2[q * 256 + tid];
            for (int i = 0; i < 128; i++) {
                int qn = (qoff + i + 1) & 127;
                float2 wfn = g_F2[qn * 256 + tid];
                const double2* hv0 = reinterpret_cast<const double2*>(hdp + (2 * q) * 8);
                const double2* hv1 = reinterpret_cast<const double2*>(hdp + (2 * q + 1) * 8);
                u64 w0 = pack2(wf.x), w1 = pack2(wf.y);
#pragma unroll
                for (int h = 0; h < 4; h++) {
                    double2 d0 = hv0[h], d1 = hv1[h];
                    fma2(f[2*h],   w0, __double_as_longlong(d0.x));
                    fma2(f[2*h+1], w0, __double_as_longlong(d0.y));
                    fma2(f[2*h],   w1, __double_as_longlong(d1.x));
                    fma2(f[2*h+1], w1, __double_as_longlong(d1.y));
                }
                wf = wfn; q = qn;
            }
#pragma unroll
            for (int p = 0; p < 8; p++) {
                float2 v = u2f(f[p]);
                f1s[(2*p)*FCH + tid]   = fmaxf(v.x + b1, 0.f);
                f1s[(2*p+1)*FCH + tid] = fmaxf(v.y + b1, 0.f);
            }
        }
        __syncthreads();

        {   // fc2: warp reduces 2 batches; carry prev in smem
#pragma unroll
            for (int bb = 0; bb < 2; bb++) {
                int b = wid * 2 + bb;
                float a = 0.f;
#pragma unroll
                for (int qq = 0; qq < 8; qq++)
                    a += f1s[b * FCH + lane + 32 * qq] * w2r[qq];
#pragma unroll
                for (int o = 16; o > 0; o >>= 1) a += __shfl_xor_sync(0xffffffffu, a, o);
                if (lane == 0) {
                    float v = a + fb;
                    out[(size_t)(B0 + b) * OL + step] = v;
                    prevs[b] = v;
                }
            }
        }
        __syncthreads();
    }
}

extern "C" void kernel_launch(void* const* d_in, const int* in_sizes, int n_in,
                              void* d_out, int out_size) {
    const float* x      = (const float*)d_in[0];
    const float* h      = (const float*)d_in[1];
    const float* eWih   = (const float*)d_in[2];
    const float* eWhh   = (const float*)d_in[3];
    const float* ebih   = (const float*)d_in[4];
    const float* ebhh   = (const float*)d_in[5];
    const float* dWih   = (const float*)d_in[6];
    const float* dWhh   = (const float*)d_in[7];
    const float* dbih   = (const float*)d_in[8];
    const float* dbhh   = (const float*)d_in[9];
    const float* wq     = (const float*)d_in[10];
    const float* bq     = (const float*)d_in[11];
    const float* fc1W   = (const float*)d_in[12];
    const float* fc1b   = (const float*)d_in[13];
    const float* fc2W   = (const float*)d_in[14];
    const float* fc2b   = (const float*)d_in[15];
    float* out = (float*)d_out;

    prep_kernel<<<256, 256>>>(x, eWih, eWhh, ebih, ebhh, dWhh, dbih, dbhh, fc1W);
    enc_all_kernel<<<BB / BM, 256>>>(x, h, wq, bq);
    dec_all_kernel<<<BB / BM, 256>>>(dWih, fc1b, fc2W, fc2b, out);
}

// round 13
// speedup vs baseline: 1.5938x; 1.0040x over previous
#include <cuda_runtime.h>
#include <cuda_fp16.h>
#include <cstdint>
#include <cstddef>

#define BB   2048
#define TT   128
#define FF   64
#define HH   256
#define OL   32
#define FCH  256
#define BMD  16      // decoder batches/block
#define BME  32      // encoder batches/block
#define SH   328     // Ash stride in halves (656B -> conflict-free A-frag loads)

// ---- device scratch ----
__device__ __half g_hsh[(size_t)TT * BB * HH];   // [t][b][j] fp16 (ctx source)
__device__ uint2  g_Bfrag[8 * 240 * 32];         // enc weights in HMMA B-fragment layout
__device__ float4 g_D6a[128 * 256];              // dec_Whh packed (fp32)
__device__ float2 g_D6b[128 * 256];
__device__ float2 g_F2 [128 * 256];              // fc1 packed (fp32)
__device__ float  g_brz[512], g_bin[256], g_bhn[256];
__device__ float  g_dbrz[512], g_dbin[256], g_dbhn[256];
__device__ float  g_Abt[(size_t)BB * TT];
__device__ float  g_Cbt[(size_t)BB * TT];
__device__ float  g_prev[BB];

typedef unsigned long long u64;

__device__ __forceinline__ void fma2(u64 &d, u64 a, u64 b) {
    asm("fma.rn.f32x2 %0, %1, %2, %0;" : "+l"(d) : "l"(a), "l"(b));
}
__device__ __forceinline__ u64 pack2(float w) {
    u64 r; unsigned int u = __float_as_uint(w);
    asm("mov.b64 %0, {%1,%1};" : "=l"(r) : "r"(u));
    return r;
}
__device__ __forceinline__ float2 u2f(u64 v) {
    float2 r;
    asm("mov.b64 {%0, %1}, %2;" : "=f"(r.x), "=f"(r.y) : "l"(v));
    return r;
}
__device__ __forceinline__ u64 hfp(unsigned v) {   // 2 fp16 -> packed f32x2
    __half2 h2 = *reinterpret_cast<__half2*>(&v);
    float2 f = __half22float2(h2);
    u64 r;
    asm("mov.b64 %0, {%1,%2};" : "=l"(r) : "f"(f.x), "f"(f.y));
    return r;
}
__device__ __forceinline__ float2 h2f(unsigned v) {
    __half2 h2 = *reinterpret_cast<__half2*>(&v);
    return __half22float2(h2);
}
__device__ __forceinline__ unsigned f2h2(float a, float b) {
    __half2 h = __floats2half2_rn(a, b);
    return *reinterpret_cast<unsigned*>(&h);
}
__device__ __forceinline__ float sigf(float x) { return 1.f / (1.f + __expf(-x)); }
__device__ __forceinline__ float tanhfast(float x) {
    float e = __expf(2.f * x);
    return (e - 1.f) * (1.f / (e + 1.f));
}

// m16n8k16 f16 MMA, fp32 accum. D/A/B fragments in standard sm_80 layout.
#define MMA4(D, A, B) \
    asm volatile("mma.sync.aligned.m16n8k16.row.col.f32.f16.f16.f32 " \
                 "{%0,%1,%2,%3},{%4,%5,%6,%7},{%8,%9},{%0,%1,%2,%3};" \
                 : "+f"((D)[0]), "+f"((D)[1]), "+f"((D)[2]), "+f"((D)[3]) \
                 : "r"((A)[0]), "r"((A)[1]), "r"((A)[2]), "r"((A)[3]), \
                   "r"((B).x), "r"((B).y))

// ---- prep: B fragments + decoder packs + bias folding + prev0 ----
__global__ void prep_kernel(const float* __restrict__ x,
                            const float* __restrict__ eWih, const float* __restrict__ eWhh,
                            const float* __restrict__ ebih, const float* __restrict__ ebhh,
                            const float* __restrict__ dWhh,
                            const float* __restrict__ dbih, const float* __restrict__ dbhh,
                            const float* __restrict__ fc1W) {
    const int stride = gridDim.x * blockDim.x;
    const int id = blockIdx.x * blockDim.x + threadIdx.x;
    // Encoder B fragments. Stream order per warp w: p = kc*12 + jgl*3 + gs
    //   gs: 0=r, 1=z, 2=(i if kc<4 else h). jg = 4w+jgl, n-cols = [8jg, 8jg+8).
    //   lane l: g=l/4, t2=(l%4)*2. b0/b1 at k=k0+t2(+1); b2/b3 at k=k0+t2+8(+9).
    for (int i = id; i < 8 * 240 * 32; i += stride) {
        int l = i & 31, pw = i >> 5;
        int p = pw % 240, w = pw / 240;
        int kc = p / 12, rr = p % 12, jgl = rr / 3, gs = rr % 3;
        int g = l >> 2, t2 = (l & 3) * 2;
        int nloc = 8 * (4 * w + jgl) + g;
        int row = (gs == 0) ? nloc : (gs == 1) ? 256 + nloc : 512 + nloc;
        int k0 = kc * 16;
        auto F = [&](int k) -> float {
            return (k < 64) ? eWih[row * 64 + k] : eWhh[row * 256 + (k - 64)];
        };
        g_Bfrag[i] = make_uint2(f2h2(F(k0 + t2),     F(k0 + t2 + 1)),
                                f2h2(F(k0 + t2 + 8), F(k0 + t2 + 9)));
    }
    // decoder packs (unchanged)
    for (int i = id; i < 128 * 256; i += stride) {
        int q = i >> 8, j = i & 255;
        int k0 = 2 * q, k1 = k0 + 1;
        g_D6a[i] = make_float4(dWhh[j * 256 + k0], dWhh[(256 + j) * 256 + k0],
                               dWhh[(512 + j) * 256 + k0], dWhh[j * 256 + k1]);
        g_D6b[i] = make_float2(dWhh[(256 + j) * 256 + k1], dWhh[(512 + j) * 256 + k1]);
        g_F2[i]  = make_float2(fc1W[j * 256 + k0], fc1W[j * 256 + k1]);
    }
    for (int i = id; i < 512; i += stride) {
        g_brz[i]  = ebih[i] + ebhh[i];
        g_dbrz[i] = dbih[i] + dbhh[i];
    }
    for (int i = id; i < 256; i += stride) {
        g_bin[i]  = ebih[512 + i];  g_bhn[i]  = ebhh[512 + i];
        g_dbin[i] = dbih[512 + i];  g_dbhn[i] = dbhh[512 + i];
    }
    for (int i = id; i < BB; i += stride)
        g_prev[i] = x[((size_t)i * TT + (TT - 1)) * FF];
}

// one k-chunk: load A frags (2 m-tiles), 12 B frags, 24 MMA. ACC3 = aI or aH.
#define KC_BODY(KC, ACC3) do {                                                   \
    const int _k0 = (KC) * 16;                                                   \
    unsigned _af[2][4];                                                          \
    _Pragma("unroll")                                                            \
    for (int _mt = 0; _mt < 2; _mt++) {                                          \
        int _mB = _mt * 16;                                                      \
        _af[_mt][0] = AshU[((_mB + g) * SH + _k0 + t2) >> 1];                    \
        _af[_mt][1] = AshU[((_mB + g + 8) * SH + _k0 + t2) >> 1];                \
        _af[_mt][2] = AshU[((_mB + g) * SH + _k0 + t2 + 8) >> 1];                \
        _af[_mt][3] = AshU[((_mB + g + 8) * SH + _k0 + t2 + 8) >> 1];            \
    }                                                                            \
    uint2 _bf[12];                                                               \
    _Pragma("unroll")                                                            \
    for (int _u = 0; _u < 12; _u++) _bf[_u] = bbase[((KC) * 12 + _u) * 32];      \
    _Pragma("unroll")                                                            \
    for (int _jg = 0; _jg < 4; _jg++) {                                          \
        MMA4(aR[_jg][0], _af[0], _bf[_jg * 3 + 0]);                              \
        MMA4(aR[_jg][1], _af[1], _bf[_jg * 3 + 0]);                              \
        MMA4(aZ[_jg][0], _af[0], _bf[_jg * 3 + 1]);                              \
        MMA4(aZ[_jg][1], _af[1], _bf[_jg * 3 + 1]);                              \
        MMA4(ACC3[_jg][0], _af[0], _bf[_jg * 3 + 2]);                            \
        MMA4(ACC3[_jg][1], _af[1], _bf[_jg * 3 + 2]);                            \
    }                                                                            \
} while (0)

// ---- persistent encoder: HMMA GEMM, in-register gates, fp16 activations ----
__global__ void __launch_bounds__(256, 1) enc_all_kernel(const float* __restrict__ x,
                                                         const float* __restrict__ h0,
                                                         const float* __restrict__ wq,
                                                         const float* __restrict__ bq) {
    __shared__ __half Ash[BME * SH];            // [m][k], k: 0-63 x, 64-319 h
    __shared__ float  sB[6 * 256];              // brz1|brz2|bin|bhn|wq|bq
    __shared__ float  redA[8 * 32], redC[8 * 32];
    unsigned* AshU = reinterpret_cast<unsigned*>(Ash);
    const int tid = threadIdx.x;
    const int w = tid >> 5, l = tid & 31;
    const int g = l >> 2, t2 = (l & 3) * 2;
    const int B0 = blockIdx.x * BME;

    sB[tid]        = g_brz[tid];
    sB[256 + tid]  = g_brz[256 + tid];
    sB[512 + tid]  = g_bin[tid];
    sB[768 + tid]  = g_bhn[tid];
    sB[1024 + tid] = wq[tid];
    sB[1280 + tid] = bq[tid];

    const int xm = tid >> 3, xk8 = (tid & 7) * 8;
    {   // init x_0 and h0 (fp32 -> fp16)
        const float4* xp = reinterpret_cast<const float4*>(
            x + ((size_t)(B0 + xm) * TT + 0) * FF + xk8);
        float4 v0 = xp[0], v1 = xp[1];
        __half2* ap = reinterpret_cast<__half2*>(&Ash[xm * SH + xk8]);
        ap[0] = __floats2half2_rn(v0.x, v0.y); ap[1] = __floats2half2_rn(v0.z, v0.w);
        ap[2] = __floats2half2_rn(v1.x, v1.y); ap[3] = __floats2half2_rn(v1.z, v1.w);
        int k32 = (tid & 7) * 32;
        const float4* hp = reinterpret_cast<const float4*>(
            h0 + (size_t)(B0 + xm) * HH + k32);
        __half2* hq = reinterpret_cast<__half2*>(&Ash[xm * SH + 64 + k32]);
#pragma unroll
        for (int qq = 0; qq < 8; qq++) {
            float4 v = hp[qq];
            hq[qq * 2]     = __floats2half2_rn(v.x, v.y);
            hq[qq * 2 + 1] = __floats2half2_rn(v.z, v.w);
        }
    }
    __syncthreads();

    const uint2* bbase = g_Bfrag + ((size_t)w * 240) * 32 + l;

    for (int t = 0; t < TT; t++) {
        // prefetch x_{t+1}
        float4 xv0, xv1;
        if (t + 1 < TT) {
            const float4* xp = reinterpret_cast<const float4*>(
                x + ((size_t)(B0 + xm) * TT + (t + 1)) * FF + xk8);
            xv0 = xp[0]; xv1 = xp[1];
        }

        float aR[4][2][4], aZ[4][2][4], aI[4][2][4], aH[4][2][4];
#pragma unroll
        for (int a = 0; a < 4; a++)
#pragma unroll
            for (int b = 0; b < 2; b++)
#pragma unroll
                for (int c = 0; c < 4; c++) {
                    aR[a][b][c] = 0.f; aZ[a][b][c] = 0.f;
                    aI[a][b][c] = 0.f; aH[a][b][c] = 0.f;
                }

        for (int kc = 0; kc < 4; kc++)  KC_BODY(kc, aI);   // x-part: r,z,i
        for (int kc = 4; kc < 20; kc++) KC_BODY(kc, aH);   // h-part: r,z,h
        __syncthreads();   // all Ash reads done

        // GRU elementwise fully in-register; update Ash; write fp16 hs; A/C partials
        float pA[4] = {0.f, 0.f, 0.f, 0.f}, pC[4] = {0.f, 0.f, 0.f, 0.f};
        __half* hshb = g_hsh + ((size_t)t * BB + B0) * HH;
#pragma unroll
        for (int jgl = 0; jgl < 4; jgl++) {
            const int j0 = 8 * (4 * w + jgl) + t2;
            float b1a = sB[j0], b1b = sB[j0 + 1];
            float b2a = sB[256 + j0], b2b = sB[257 + j0];
            float bia = sB[512 + j0], bib = sB[513 + j0];
            float bha = sB[768 + j0], bhb = sB[769 + j0];
            float wqa = sB[1024 + j0], wqb = sB[1025 + j0];
            float bqa = sB[1280 + j0], bqb = sB[1281 + j0];
#pragma unroll
            for (int mt = 0; mt < 2; mt++) {
#pragma unroll
                for (int rr = 0; rr < 2; rr++) {
                    const int m = mt * 16 + g + rr * 8;
                    float Rv0 = aR[jgl][mt][rr * 2], Rv1 = aR[jgl][mt][rr * 2 + 1];
                    float Zv0 = aZ[jgl][mt][rr * 2], Zv1 = aZ[jgl][mt][rr * 2 + 1];
                    float Iv0 = aI[jgl][mt][rr * 2], Iv1 = aI[jgl][mt][rr * 2 + 1];
                    float Hv0 = aH[jgl][mt][rr * 2], Hv1 = aH[jgl][mt][rr * 2 + 1];
                    float2 hpf = h2f(AshU[(m * SH + 64 + j0) >> 1]);
                    float r0 = sigf(Rv0 + b1a), z0 = sigf(Zv0 + b2a);
                    float n0 = tanhfast(Iv0 + bia + r0 * (Hv0 + bha));
                    float h0n = (1.f - z0) * n0 + z0 * hpf.x;
                    float r1 = sigf(Rv1 + b1b), z1 = sigf(Zv1 + b2b);
                    float n1 = tanhfast(Iv1 + bib + r1 * (Hv1 + bhb));
                    float h1n = (1.f - z1) * n1 + z1 * hpf.y;
                    unsigned packed = f2h2(h0n, h1n);
                    AshU[(m * SH + 64 + j0) >> 1] = packed;
                    reinterpret_cast<unsigned*>(hshb)[(m * HH + j0) >> 1] = packed;
                    pA[mt * 2 + rr] += wqa * h0n + wqb * h1n;
                    pC[mt * 2 + rr] += bqa * h0n + bqb * h1n;
                }
            }
        }
        // store x_{t+1}
        if (t + 1 < TT) {
            __half2* ap = reinterpret_cast<__half2*>(&Ash[xm * SH + xk8]);
            ap[0] = __floats2half2_rn(xv0.x, xv0.y); ap[1] = __floats2half2_rn(xv0.z, xv0.w);
            ap[2] = __floats2half2_rn(xv1.x, xv1.y); ap[3] = __floats2half2_rn(xv1.z, xv1.w);
        }
        // quad-reduce A/C partials (lanes sharing g)
#pragma unroll
        for (int o = 1; o <= 2; o <<= 1) {
#pragma unroll
            for (int qv = 0; qv < 4; qv++) {
                pA[qv] += __shfl_xor_sync(0xffffffffu, pA[qv], o);
                pC[qv] += __shfl_xor_sync(0xffffffffu, pC[qv], o);
            }
        }
        if ((l & 3) == 0) {
#pragma unroll
            for (int qv = 0; qv < 4; qv++) {
                int m = (qv >> 1) * 16 + g + (qv & 1) * 8;
                redA[w * 32 + m] = pA[qv];
                redC[w * 32 + m] = pC[qv];
            }
        }
        __syncthreads();   // Ash writes + redA/redC visible

        if (tid < 64) {    // finalize A/C (32 m x {A,C})
            int m = tid & 31;
            bool isC = tid >= 32;
            float s = 0.f;
#pragma unroll
            for (int ww = 0; ww < 8; ww++)
                s += (isC ? redC : redA)[ww * 32 + m];
            (isC ? g_Cbt : g_Abt)[(size_t)(B0 + m) * TT + t] = s * 0.0625f;
        }
    }
}

#define DEC_STEP6(K0) do {                                                                 \
    const double2* _av0 = reinterpret_cast<const double2*>(ctxp + (K0) * 8);               \
    const double2* _av1 = reinterpret_cast<const double2*>(ctxp + ((K0) + 1) * 8);         \
    u64 _p00 = pack2(wa.x), _p01 = pack2(wa.y), _p02 = pack2(wa.z);                        \
    u64 _p10 = pack2(wa.w), _p11 = pack2(wb.x), _p12 = pack2(wb.y);                        \
    _Pragma("unroll")                                                                      \
    for (int _h = 0; _h < 4; _h++) {                                                       \
        double2 _d0 = _av0[_h], _d1 = _av1[_h];                                            \
        u64 _a00 = __double_as_longlong(_d0.x), _a01 = __double_as_longlong(_d0.y);        \
        u64 _a10 = __double_as_longlong(_d1.x), _a11 = __double_as_longlong(_d1.y);        \
        fma2(ar[2*_h],   _p00, _a00); fma2(az[2*_h],   _p01, _a00); fma2(an[2*_h],   _p02, _a00); \
        fma2(ar[2*_h+1], _p00, _a01); fma2(az[2*_h+1], _p01, _a01); fma2(an[2*_h+1], _p02, _a01); \
        fma2(ar[2*_h],   _p10, _a10); fma2(az[2*_h],   _p11, _a10); fma2(an[2*_h],   _p12, _a10); \
        fma2(ar[2*_h+1], _p10, _a11); fma2(az[2*_h+1], _p11, _a11); fma2(an[2*_h+1], _p12, _a11); \
    }                                                                                      \
} while (0)

// ---- persistent decoder: all 32 steps fused (proven R12 version) ----
__global__ void __launch_bounds__(256) dec_all_kernel(const float* __restrict__ dWih,
                                                      const float* __restrict__ fc1b,
                                                      const float* __restrict__ fc2W,
                                                      const float* __restrict__ fc2b,
                                                      float* __restrict__ out) {
    __shared__ char smraw[8192 + 16384 + 16384 + 64];
    float*  s     = reinterpret_cast<float*>(smraw);
    float2* ctxp  = reinterpret_cast<float2*>(smraw + 8192);
    float*  f1s   = reinterpret_cast<float*>(smraw + 8192);
    float2* hdp   = reinterpret_cast<float2*>(smraw + 8192 + 16384);
    float*  prevs = reinterpret_cast<float*>(smraw + 8192 + 32768);
    const int tid = threadIdx.x;
    const int B0 = blockIdx.x * BMD;
    const int wid = tid >> 5, lane = tid & 31;
    const int j = tid;
    const int toff = (blockIdx.x * 29) & 127;
    const int qoff = (blockIdx.x * 13) & 127;

    if (tid < BMD) prevs[tid] = g_prev[B0 + tid];
    const float dwr = dWih[j], dwz = dWih[256 + j], dwn = dWih[512 + j];
    const float br = g_dbrz[j], bz = g_dbrz[256 + j], bi = g_dbin[j], bh = g_dbhn[j];
    const float b1 = fc1b[tid], fb = fc2b[0];
    float w2r[8];
#pragma unroll
    for (int qq = 0; qq < 8; qq++) w2r[qq] = fc2W[lane + 32 * qq];
    __syncthreads();

    for (int step = 0; step < OL; step++) {
        for (int i = tid; i < BMD * TT; i += 256) {
            int b = i >> 7;
            s[i] = prevs[b] * g_Abt[(size_t)B0 * TT + i] + g_Cbt[(size_t)B0 * TT + i];
        }
        __syncthreads();

#pragma unroll
        for (int bb = 0; bb < 2; bb++) {
            int b = wid * 2 + bb;
            float v0 = s[b*TT+lane], v1 = s[b*TT+lane+32], v2 = s[b*TT+lane+64], v3 = s[b*TT+lane+96];
            float m = fmaxf(fmaxf(v0, v1), fmaxf(v2, v3));
#pragma unroll
            for (int o = 16; o > 0; o >>= 1) m = fmaxf(m, __shfl_xor_sync(0xffffffffu, m, o));
            float e0 = __expf(v0-m), e1 = __expf(v1-m), e2 = __expf(v2-m), e3 = __expf(v3-m);
            float sum = e0 + e1 + e2 + e3;
#pragma unroll
            for (int o = 16; o > 0; o >>= 1) sum += __shfl_xor_sync(0xffffffffu, sum, o);
            float inv = 1.f / sum;
            s[b*TT+lane] = e0*inv; s[b*TT+lane+32] = e1*inv; s[b*TT+lane+64] = e2*inv; s[b*TT+lane+96] = e3*inv;
        }
        __syncthreads();

        {   // ctx pass over fp16 hs
            const int jv = (tid & 63) * 4;
            const int bs = tid >> 6;
            u64 c0[2] = {0,0}, c1[2] = {0,0}, c2[2] = {0,0}, c3[2] = {0,0};
#pragma unroll 4
            for (int i = 0; i < TT; i++) {
                int t = (i + toff) & 127;
                const uint2* hb = reinterpret_cast<const uint2*>(
                    g_hsh + ((size_t)t * BB + B0) * HH) + (jv >> 2);
                float w0 = s[(bs+0)*TT+t], w1 = s[(bs+4)*TT+t], w2 = s[(bs+8)*TT+t], w3 = s[(bs+12)*TT+t];
                uint2 v0 = hb[(bs+0)*64], v1 = hb[(bs+4)*64], v2 = hb[(bs+8)*64], v3 = hb[(bs+12)*64];
                u64 wp0 = pack2(w0), wp1 = pack2(w1), wp2 = pack2(w2), wp3 = pack2(w3);
                fma2(c0[0], wp0, hfp(v0.x)); fma2(c0[1], wp0, hfp(v0.y));
                fma2(c1[0], wp1, hfp(v1.x)); fma2(c1[1], wp1, hfp(v1.y));
                fma2(c2[0], wp2, hfp(v2.x)); fma2(c2[1], wp2, hfp(v2.y));
                fma2(c3[0], wp3, hfp(v3.x)); fma2(c3[1], wp3, hfp(v3.y));
            }
            float* cf = reinterpret_cast<float*>(ctxp);
            u64* cc[4] = {c0, c1, c2, c3};
#pragma unroll
            for (int qq = 0; qq < 4; qq++) {
                int b = bs + 4 * qq, p = b >> 1, par = b & 1;
                float2 lo = u2f(cc[qq][0]), hi = u2f(cc[qq][1]);
                cf[((jv+0)*8+p)*2+par] = lo.x; cf[((jv+1)*8+p)*2+par] = lo.y;
                cf[((jv+2)*8+p)*2+par] = hi.x; cf[((jv+3)*8+p)*2+par] = hi.y;
            }
        }
        __syncthreads();

        u64 ar[8], az[8], an[8];
#pragma unroll
        for (int p = 0; p < 8; p++) { ar[p] = 0; az[p] = 0; an[p] = 0; }
        {
            int q = qoff;
            float4 wa = g_D6a[q * 256 + tid];
            float2 wb = g_D6b[q * 256 + tid];
            for (int i = 0; i < 128; i++) {
                int qn = (qoff + i + 1) & 127;
                float4 wan = g_D6a[qn * 256 + tid];
                float2 wbn = g_D6b[qn * 256 + tid];
                DEC_STEP6(2 * q);
                wa = wan; wb = wbn; q = qn;
            }
        }
        {
#pragma unroll
            for (int p = 0; p < 8; p++) {
                float2 fr = u2f(ar[p]), fz = u2f(az[p]), fn = u2f(an[p]);
                float2 cx = ctxp[j * 8 + p];
                float2 hd;
                float pv = prevs[2 * p];
                float r = sigf(pv * dwr + fr.x + br);
                float z = sigf(pv * dwz + fz.x + bz);
                float n = tanhf(pv * dwn + bi + r * (fn.x + bh));
                hd.x = (1.f - z) * n + z * cx.x;
                pv = prevs[2 * p + 1];
                r = sigf(pv * dwr + fr.y + br);
                z = sigf(pv * dwz + fz.y + bz);
                n = tanhf(pv * dwn + bi + r * (fn.y + bh));
                hd.y = (1.f - z) * n + z * cx.y;
                hdp[j * 8 + p] = hd;
            }
        }
        __syncthreads();

        {
            u64 f[8];
#pragma unroll
            for (int p = 0; p < 8; p++) f[p] = 0;
            int q = qoff;
            float2 wf = g_F2[q * 256 + tid];
            for (int i = 0; i < 128; i++) {
                int qn = (qoff + i + 1) & 127;
                float2 wfn = g_F2[qn * 256 + tid];
                const double2* hv0 = reinterpret_cast<const double2*>(hdp + (2 * q) * 8);
                const double2* hv1 = reinterpret_cast<const double2*>(hdp + (2 * q + 1) * 8);
                u64 w0 = pack2(wf.x), w1 = pack2(wf.y);
#pragma unroll
                for (int h = 0; h < 4; h++) {
                    double2 d0 = hv0[h], d1 = hv1[h];
                    fma2(f[2*h],   w0, __double_as_longlong(d0.x));
                    fma2(f[2*h+1], w0, __double_as_longlong(d0.y));
                    fma2(f[2*h],   w1, __double_as_longlong(d1.x));
                    fma2(f[2*h+1], w1, __double_as_longlong(d1.y));
                }
                wf = wfn; q = qn;
            }
#pragma unroll
            for (int p = 0; p < 8; p++) {
                float2 v = u2f(f[p]);
                f1s[(2*p)*FCH + tid]   = fmaxf(v.x + b1, 0.f);
                f1s[(2*p+1)*FCH + tid] = fmaxf(v.y + b1, 0.f);
            }
        }
        __syncthreads();

        {
#pragma unroll
            for (int bb = 0; bb < 2; bb++) {
                int b = wid * 2 + bb;
                float a = 0.f;
#pragma unroll
                for (int qq = 0; qq < 8; qq++)
                    a += f1s[b * FCH + lane + 32 * qq] * w2r[qq];
#pragma unroll
                for (int o = 16; o > 0; o >>= 1) a += __shfl_xor_sync(0xffffffffu, a, o);
                if (lane == 0) {
                    float v = a + fb;
                    out[(size_t)(B0 + b) * OL + step] = v;
                    prevs[b] = v;
                }
            }
        }
        __syncthreads();
    }
}

extern "C" void kernel_launch(void* const* d_in, const int* in_sizes, int n_in,
                              void* d_out, int out_size) {
    const float* x      = (const float*)d_in[0];
    const float* h      = (const float*)d_in[1];
    const float* eWih   = (const float*)d_in[2];
    const float* eWhh   = (const float*)d_in[3];
    const float* ebih   = (const float*)d_in[4];
    const float* ebhh   = (const float*)d_in[5];
    const float* dWih   = (const float*)d_in[6];
    const float* dWhh   = (const float*)d_in[7];
    const float* dbih   = (const float*)d_in[8];
    const float* dbhh   = (const float*)d_in[9];
    const float* wq     = (const float*)d_in[10];
    const float* bq     = (const float*)d_in[11];
    const float* fc1W   = (const float*)d_in[12];
    const float* fc1b   = (const float*)d_in[13];
    const float* fc2W   = (const float*)d_in[14];
    const float* fc2b   = (const float*)d_in[15];
    float* out = (float*)d_out;

    prep_kernel<<<256, 256>>>(x, eWih, eWhh, ebih, ebhh, dWhh, dbih, dbhh, fc1W);
    enc_all_kernel<<<BB / BME, 256>>>(x, h, wq, bq);
    dec_all_kernel<<<BB / BMD, 256>>>(dWih, fc1b, fc2W, fc2b, out);
}

// round 14
// speedup vs baseline: 1.5957x; 1.0012x over previous
#include <cuda_runtime.h>
#include <cuda_fp16.h>
#include <cstdint>
#include <cstddef>

#define BB   2048
#define TT   128
#define FF   64
#define HH   256
#define OL   32
#define FCH  256
#define BMD  16      // decoder batches/block
#define BME  32      // encoder batches/block
#define SH   328     // Ash stride in halves (656B -> conflict-free A-frag loads)

// ---- device scratch ----
__device__ __half g_hsh[(size_t)TT * BB * HH];   // [t][b][j] fp16 (ctx source)
__device__ uint2  g_Bfrag[8 * 240 * 32];         // enc weights in HMMA B-fragment layout
__device__ float4 g_D6a[128 * 256];              // dec_Whh packed (fp32)
__device__ float2 g_D6b[128 * 256];
__device__ float2 g_F2 [128 * 256];              // fc1 packed (fp32)
__device__ float  g_brz[512], g_bin[256], g_bhn[256];
__device__ float  g_dbrz[512], g_dbin[256], g_dbhn[256];
__device__ float  g_Abt[(size_t)BB * TT];
__device__ float  g_Cbt[(size_t)BB * TT];
__device__ float  g_prev[BB];

typedef unsigned long long u64;

__device__ __forceinline__ void fma2(u64 &d, u64 a, u64 b) {
    asm("fma.rn.f32x2 %0, %1, %2, %0;" : "+l"(d) : "l"(a), "l"(b));
}
__device__ __forceinline__ u64 pack2(float w) {
    u64 r; unsigned int u = __float_as_uint(w);
    asm("mov.b64 %0, {%1,%1};" : "=l"(r) : "r"(u));
    return r;
}
__device__ __forceinline__ float2 u2f(u64 v) {
    float2 r;
    asm("mov.b64 {%0, %1}, %2;" : "=f"(r.x), "=f"(r.y) : "l"(v));
    return r;
}
__device__ __forceinline__ u64 hfp(unsigned v) {   // 2 fp16 -> packed f32x2
    __half2 h2 = *reinterpret_cast<__half2*>(&v);
    float2 f = __half22float2(h2);
    u64 r;
    asm("mov.b64 %0, {%1,%2};" : "=l"(r) : "f"(f.x), "f"(f.y));
    return r;
}
__device__ __forceinline__ float2 h2f(unsigned v) {
    __half2 h2 = *reinterpret_cast<__half2*>(&v);
    return __half22float2(h2);
}
__device__ __forceinline__ unsigned f2h2(float a, float b) {
    __half2 h = __floats2half2_rn(a, b);
    return *reinterpret_cast<unsigned*>(&h);
}
__device__ __forceinline__ float sigf(float x) { return 1.f / (1.f + __expf(-x)); }
__device__ __forceinline__ float tanhfast(float x) {
    float e = __expf(2.f * x);
    return (e - 1.f) * (1.f / (e + 1.f));
}

// m16n8k16 f16 MMA, fp32 accum. D/A/B fragments in standard sm_80 layout.
#define MMA4(D, A, B) \
    asm volatile("mma.sync.aligned.m16n8k16.row.col.f32.f16.f16.f32 " \
                 "{%0,%1,%2,%3},{%4,%5,%6,%7},{%8,%9},{%0,%1,%2,%3};" \
                 : "+f"((D)[0]), "+f"((D)[1]), "+f"((D)[2]), "+f"((D)[3]) \
                 : "r"((A)[0]), "r"((A)[1]), "r"((A)[2]), "r"((A)[3]), \
                   "r"((B).x), "r"((B).y))

// ---- prep: B fragments + decoder packs + bias folding + prev0 ----
__global__ void prep_kernel(const float* __restrict__ x,
                            const float* __restrict__ eWih, const float* __restrict__ eWhh,
                            const float* __restrict__ ebih, const float* __restrict__ ebhh,
                            const float* __restrict__ dWhh,
                            const float* __restrict__ dbih, const float* __restrict__ dbhh,
                            const float* __restrict__ fc1W) {
    const int stride = gridDim.x * blockDim.x;
    const int id = blockIdx.x * blockDim.x + threadIdx.x;
    // Encoder B fragments. Stream order per warp w: p = kc*12 + jgl*3 + gs
    //   gs: 0=r, 1=z, 2=(i if kc<4 else h). jg = 4w+jgl, n-cols = [8jg, 8jg+8).
    //   lane l: g=l/4, t2=(l%4)*2. b0/b1 at k=k0+t2(+1); b2/b3 at k=k0+t2+8(+9).
    for (int i = id; i < 8 * 240 * 32; i += stride) {
        int l = i & 31, pw = i >> 5;
        int p = pw % 240, w = pw / 240;
        int kc = p / 12, rr = p % 12, jgl = rr / 3, gs = rr % 3;
        int g = l >> 2, t2 = (l & 3) * 2;
        int nloc = 8 * (4 * w + jgl) + g;
        int row = (gs == 0) ? nloc : (gs == 1) ? 256 + nloc : 512 + nloc;
        int k0 = kc * 16;
        auto F = [&](int k) -> float {
            return (k < 64) ? eWih[row * 64 + k] : eWhh[row * 256 + (k - 64)];
        };
        g_Bfrag[i] = make_uint2(f2h2(F(k0 + t2),     F(k0 + t2 + 1)),
                                f2h2(F(k0 + t2 + 8), F(k0 + t2 + 9)));
    }
    // decoder packs (unchanged)
    for (int i = id; i < 128 * 256; i += stride) {
        int q = i >> 8, j = i & 255;
        int k0 = 2 * q, k1 = k0 + 1;
        g_D6a[i] = make_float4(dWhh[j * 256 + k0], dWhh[(256 + j) * 256 + k0],
                               dWhh[(512 + j) * 256 + k0], dWhh[j * 256 + k1]);
        g_D6b[i] = make_float2(dWhh[(256 + j) * 256 + k1], dWhh[(512 + j) * 256 + k1]);
        g_F2[i]  = make_float2(fc1W[j * 256 + k0], fc1W[j * 256 + k1]);
    }
    for (int i = id; i < 512; i += stride) {
        g_brz[i]  = ebih[i] + ebhh[i];
        g_dbrz[i] = dbih[i] + dbhh[i];
    }
    for (int i = id; i < 256; i += stride) {
        g_bin[i]  = ebih[512 + i];  g_bhn[i]  = ebhh[512 + i];
        g_dbin[i] = dbih[512 + i];  g_dbhn[i] = dbhh[512 + i];
    }
    for (int i = id; i < BB; i += stride)
        g_prev[i] = x[((size_t)i * TT + (TT - 1)) * FF];
}

// one k-chunk: load A frags (2 m-tiles), 12 B frags, 24 MMA. ACC3 = aI or aH.
#define KC_BODY(KC, ACC3) do {                                                   \
    const int _k0 = (KC) * 16;                                                   \
    unsigned _af[2][4];                                                          \
    _Pragma("unroll")                                                            \
    for (int _mt = 0; _mt < 2; _mt++) {                                          \
        int _mB = _mt * 16;                                                      \
        _af[_mt][0] = AshU[((_mB + g) * SH + _k0 + t2) >> 1];                    \
        _af[_mt][1] = AshU[((_mB + g + 8) * SH + _k0 + t2) >> 1];                \
        _af[_mt][2] = AshU[((_mB + g) * SH + _k0 + t2 + 8) >> 1];                \
        _af[_mt][3] = AshU[((_mB + g + 8) * SH + _k0 + t2 + 8) >> 1];            \
    }                                                                            \
    uint2 _bf[12];                                                               \
    _Pragma("unroll")                                                            \
    for (int _u = 0; _u < 12; _u++) _bf[_u] = bbase[((KC) * 12 + _u) * 32];      \
    _Pragma("unroll")                                                            \
    for (int _jg = 0; _jg < 4; _jg++) {                                          \
        MMA4(aR[_jg][0], _af[0], _bf[_jg * 3 + 0]);                              \
        MMA4(aR[_jg][1], _af[1], _bf[_jg * 3 + 0]);                              \
        MMA4(aZ[_jg][0], _af[0], _bf[_jg * 3 + 1]);                              \
        MMA4(aZ[_jg][1], _af[1], _bf[_jg * 3 + 1]);                              \
        MMA4(ACC3[_jg][0], _af[0], _bf[_jg * 3 + 2]);                            \
        MMA4(ACC3[_jg][1], _af[1], _bf[_jg * 3 + 2]);                            \
    }                                                                            \
} while (0)

// ---- persistent encoder: HMMA GEMM, in-register gates, fp16 activations ----
__global__ void __launch_bounds__(256, 1) enc_all_kernel(const float* __restrict__ x,
                                                         const float* __restrict__ h0,
                                                         const float* __restrict__ wq,
                                                         const float* __restrict__ bq) {
    __shared__ __half Ash[BME * SH];            // [m][k], k: 0-63 x, 64-319 h
    __shared__ float  sB[6 * 256];              // brz1|brz2|bin|bhn|wq|bq
    __shared__ float  redA[8 * 32], redC[8 * 32];
    unsigned* AshU = reinterpret_cast<unsigned*>(Ash);
    const int tid = threadIdx.x;
    const int w = tid >> 5, l = tid & 31;
    const int g = l >> 2, t2 = (l & 3) * 2;
    const int B0 = blockIdx.x * BME;

    sB[tid]        = g_brz[tid];
    sB[256 + tid]  = g_brz[256 + tid];
    sB[512 + tid]  = g_bin[tid];
    sB[768 + tid]  = g_bhn[tid];
    sB[1024 + tid] = wq[tid];
    sB[1280 + tid] = bq[tid];

    const int xm = tid >> 3, xk8 = (tid & 7) * 8;
    {   // init x_0 and h0 (fp32 -> fp16)
        const float4* xp = reinterpret_cast<const float4*>(
            x + ((size_t)(B0 + xm) * TT + 0) * FF + xk8);
        float4 v0 = xp[0], v1 = xp[1];
        __half2* ap = reinterpret_cast<__half2*>(&Ash[xm * SH + xk8]);
        ap[0] = __floats2half2_rn(v0.x, v0.y); ap[1] = __floats2half2_rn(v0.z, v0.w);
        ap[2] = __floats2half2_rn(v1.x, v1.y); ap[3] = __floats2half2_rn(v1.z, v1.w);
        int k32 = (tid & 7) * 32;
        const float4* hp = reinterpret_cast<const float4*>(
            h0 + (size_t)(B0 + xm) * HH + k32);
        __half2* hq = reinterpret_cast<__half2*>(&Ash[xm * SH + 64 + k32]);
#pragma unroll
        for (int qq = 0; qq < 8; qq++) {
            float4 v = hp[qq];
            hq[qq * 2]     = __floats2half2_rn(v.x, v.y);
            hq[qq * 2 + 1] = __floats2half2_rn(v.z, v.w);
        }
    }
    __syncthreads();

    const uint2* bbase = g_Bfrag + ((size_t)w * 240) * 32 + l;

    for (int t = 0; t < TT; t++) {
        // prefetch x_{t+1}
        float4 xv0, xv1;
        if (t + 1 < TT) {
            const float4* xp = reinterpret_cast<const float4*>(
                x + ((size_t)(B0 + xm) * TT + (t + 1)) * FF + xk8);
            xv0 = xp[0]; xv1 = xp[1];
        }

        float aR[4][2][4], aZ[4][2][4], aI[4][2][4], aH[4][2][4];
#pragma unroll
        for (int a = 0; a < 4; a++)
#pragma unroll
            for (int b = 0; b < 2; b++)
#pragma unroll
                for (int c = 0; c < 4; c++) {
                    aR[a][b][c] = 0.f; aZ[a][b][c] = 0.f;
                    aI[a][b][c] = 0.f; aH[a][b][c] = 0.f;
                }

        for (int kc = 0; kc < 4; kc++)  KC_BODY(kc, aI);   // x-part: r,z,i
        for (int kc = 4; kc < 20; kc++) KC_BODY(kc, aH);   // h-part: r,z,h
        __syncthreads();   // all Ash reads done

        // GRU elementwise fully in-register; update Ash; write fp16 hs; A/C partials
        float pA[4] = {0.f, 0.f, 0.f, 0.f}, pC[4] = {0.f, 0.f, 0.f, 0.f};
        __half* hshb = g_hsh + ((size_t)t * BB + B0) * HH;
#pragma unroll
        for (int jgl = 0; jgl < 4; jgl++) {
            const int j0 = 8 * (4 * w + jgl) + t2;
            float b1a = sB[j0], b1b = sB[j0 + 1];
            float b2a = sB[256 + j0], b2b = sB[257 + j0];
            float bia = sB[512 + j0], bib = sB[513 + j0];
            float bha = sB[768 + j0], bhb = sB[769 + j0];
            float wqa = sB[1024 + j0], wqb = sB[1025 + j0];
            float bqa = sB[1280 + j0], bqb = sB[1281 + j0];
#pragma unroll
            for (int mt = 0; mt < 2; mt++) {
#pragma unroll
                for (int rr = 0; rr < 2; rr++) {
                    const int m = mt * 16 + g + rr * 8;
                    float Rv0 = aR[jgl][mt][rr * 2], Rv1 = aR[jgl][mt][rr * 2 + 1];
                    float Zv0 = aZ[jgl][mt][rr * 2], Zv1 = aZ[jgl][mt][rr * 2 + 1];
                    float Iv0 = aI[jgl][mt][rr * 2], Iv1 = aI[jgl][mt][rr * 2 + 1];
                    float Hv0 = aH[jgl][mt][rr * 2], Hv1 = aH[jgl][mt][rr * 2 + 1];
                    float2 hpf = h2f(AshU[(m * SH + 64 + j0) >> 1]);
                    float r0 = sigf(Rv0 + b1a), z0 = sigf(Zv0 + b2a);
                    float n0 = tanhfast(Iv0 + bia + r0 * (Hv0 + bha));
                    float h0n = (1.f - z0) * n0 + z0 * hpf.x;
                    float r1 = sigf(Rv1 + b1b), z1 = sigf(Zv1 + b2b);
                    float n1 = tanhfast(Iv1 + bib + r1 * (Hv1 + bhb));
                    float h1n = (1.f - z1) * n1 + z1 * hpf.y;
                    unsigned packed = f2h2(h0n, h1n);
                    AshU[(m * SH + 64 + j0) >> 1] = packed;
                    reinterpret_cast<unsigned*>(hshb)[(m * HH + j0) >> 1] = packed;
                    pA[mt * 2 + rr] += wqa * h0n + wqb * h1n;
                    pC[mt * 2 + rr] += bqa * h0n + bqb * h1n;
                }
            }
        }
        // store x_{t+1}
        if (t + 1 < TT) {
            __half2* ap = reinterpret_cast<__half2*>(&Ash[xm * SH + xk8]);
            ap[0] = __floats2half2_rn(xv0.x, xv0.y); ap[1] = __floats2half2_rn(xv0.z, xv0.w);
            ap[2] = __floats2half2_rn(xv1.x, xv1.y); ap[3] = __floats2half2_rn(xv1.z, xv1.w);
        }
        // quad-reduce A/C partials (lanes sharing g)
#pragma unroll
        for (int o = 1; o <= 2; o <<= 1) {
#pragma unroll
            for (int qv = 0; qv < 4; qv++) {
                pA[qv] += __shfl_xor_sync(0xffffffffu, pA[qv], o);
                pC[qv] += __shfl_xor_sync(0xffffffffu, pC[qv], o);
            }
        }
        if ((l & 3) == 0) {
#pragma unroll
            for (int qv = 0; qv < 4; qv++) {
                int m = (qv >> 1) * 16 + g + (qv & 1) * 8;
                redA[w * 32 + m] = pA[qv];
                redC[w * 32 + m] = pC[qv];
            }
        }
        __syncthreads();   // Ash writes + redA/redC visible

        if (tid < 64) {    // finalize A/C (32 m x {A,C})
            int m = tid & 31;
            bool isC = tid >= 32;
            float s = 0.f;
#pragma unroll
            for (int ww = 0; ww < 8; ww++)
                s += (isC ? redC : redA)[ww * 32 + m];
            (isC ? g_Cbt : g_Abt)[(size_t)(B0 + m) * TT + t] = s * 0.0625f;
        }
    }
}

#define DEC_STEP6(K0) do {                                                                 \
    const double2* _av0 = reinterpret_cast<const double2*>(ctxp + (K0) * 8);               \
    const double2* _av1 = reinterpret_cast<const double2*>(ctxp + ((K0) + 1) * 8);         \
    u64 _p00 = pack2(wa.x), _p01 = pack2(wa.y), _p02 = pack2(wa.z);                        \
    u64 _p10 = pack2(wa.w), _p11 = pack2(wb.x), _p12 = pack2(wb.y);                        \
    _Pragma("unroll")                                                                      \
    for (int _h = 0; _h < 4; _h++) {                                                       \
        double2 _d0 = _av0[_h], _d1 = _av1[_h];                                            \
        u64 _a00 = __double_as_longlong(_d0.x), _a01 = __double_as_longlong(_d0.y);        \
        u64 _a10 = __double_as_longlong(_d1.x), _a11 = __double_as_longlong(_d1.y);        \
        fma2(ar[2*_h],   _p00, _a00); fma2(az[2*_h],   _p01, _a00); fma2(an[2*_h],   _p02, _a00); \
        fma2(ar[2*_h+1], _p00, _a01); fma2(az[2*_h+1], _p01, _a01); fma2(an[2*_h+1], _p02, _a01); \
        fma2(ar[2*_h],   _p10, _a10); fma2(az[2*_h],   _p11, _a10); fma2(an[2*_h],   _p12, _a10); \
        fma2(ar[2*_h+1], _p10, _a11); fma2(az[2*_h+1], _p11, _a11); fma2(an[2*_h+1], _p12, _a11); \
    }                                                                                      \
} while (0)

// ---- persistent decoder: all 32 steps fused (proven R12 version) ----
__global__ void __launch_bounds__(256) dec_all_kernel(const float* __restrict__ dWih,
                                                      const float* __restrict__ fc1b,
                                                      const float* __restrict__ fc2W,
                                                      const float* __restrict__ fc2b,
                                                      float* __restrict__ out) {
    __shared__ char smraw[8192 + 16384 + 16384 + 64];
    float*  s     = reinterpret_cast<float*>(smraw);
    float2* ctxp  = reinterpret_cast<float2*>(smraw + 8192);
    float*  f1s   = reinterpret_cast<float*>(smraw + 8192);
    float2* hdp   = reinterpret_cast<float2*>(smraw + 8192 + 16384);
    float*  prevs = reinterpret_cast<float*>(smraw + 8192 + 32768);
    const int tid = threadIdx.x;
    const int B0 = blockIdx.x * BMD;
    const int wid = tid >> 5, lane = tid & 31;
    const int j = tid;
    const int toff = (blockIdx.x * 29) & 127;
    const int qoff = (blockIdx.x * 13) & 127;

    if (tid < BMD) prevs[tid] = g_prev[B0 + tid];
    const float dwr = dWih[j], dwz = dWih[256 + j], dwn = dWih[512 + j];
    const float br = g_dbrz[j], bz = g_dbrz[256 + j], bi = g_dbin[j], bh = g_dbhn[j];
    const float b1 = fc1b[tid], fb = fc2b[0];
    float w2r[8];
#pragma unroll
    for (int qq = 0; qq < 8; qq++) w2r[qq] = fc2W[lane + 32 * qq];
    __syncthreads();

    for (int step = 0; step < OL; step++) {
        for (int i = tid; i < BMD * TT; i += 256) {
            int b = i >> 7;
            s[i] = prevs[b] * g_Abt[(size_t)B0 * TT + i] + g_Cbt[(size_t)B0 * TT + i];
        }
        __syncthreads();

#pragma unroll
        for (int bb = 0; bb < 2; bb++) {
            int b = wid * 2 + bb;
            float v0 = s[b*TT+lane], v1 = s[b*TT+lane+32], v2 = s[b*TT+lane+64], v3 = s[b*TT+lane+96];
            float m = fmaxf(fmaxf(v0, v1), fmaxf(v2, v3));
#pragma unroll
            for (int o = 16; o > 0; o >>= 1) m = fmaxf(m, __shfl_xor_sync(0xffffffffu, m, o));
            float e0 = __expf(v0-m), e1 = __expf(v1-m), e2 = __expf(v2-m), e3 = __expf(v3-m);
            float sum = e0 + e1 + e2 + e3;
#pragma unroll
            for (int o = 16; o > 0; o >>= 1) sum += __shfl_xor_sync(0xffffffffu, sum, o);
            float inv = 1.f / sum;
            s[b*TT+lane] = e0*inv; s[b*TT+lane+32] = e1*inv; s[b*TT+lane+64] = e2*inv; s[b*TT+lane+96] = e3*inv;
        }
        __syncthreads();

        {   // ctx pass over fp16 hs
            const int jv = (tid & 63) * 4;
            const int bs = tid >> 6;
            u64 c0[2] = {0,0}, c1[2] = {0,0}, c2[2] = {0,0}, c3[2] = {0,0};
#pragma unroll 4
            for (int i = 0; i < TT; i++) {
                int t = (i + toff) & 127;
                const uint2* hb = reinterpret_cast<const uint2*>(
                    g_hsh + ((size_t)t * BB + B0) * HH) + (jv >> 2);
                float w0 = s[(bs+0)*TT+t], w1 = s[(bs+4)*TT+t], w2 = s[(bs+8)*TT+t], w3 = s[(bs+12)*TT+t];
                uint2 v0 = hb[(bs+0)*64], v1 = hb[(bs+4)*64], v2 = hb[(bs+8)*64], v3 = hb[(bs+12)*64];
                u64 wp0 = pack2(w0), wp1 = pack2(w1), wp2 = pack2(w2), wp3 = pack2(w3);
                fma2(c0[0], wp0, hfp(v0.x)); fma2(c0[1], wp0, hfp(v0.y));
                fma2(c1[0], wp1, hfp(v1.x)); fma2(c1[1], wp1, hfp(v1.y));
                fma2(c2[0], wp2, hfp(v2.x)); fma2(c2[1], wp2, hfp(v2.y));
                fma2(c3[0], wp3, hfp(v3.x)); fma2(c3[1], wp3, hfp(v3.y));
            }
            float* cf = reinterpret_cast<float*>(ctxp);
            u64* cc[4] = {c0, c1, c2, c3};
#pragma unroll
            for (int qq = 0; qq < 4; qq++) {
                int b = bs + 4 * qq, p = b >> 1, par = b & 1;
                float2 lo = u2f(cc[qq][0]), hi = u2f(cc[qq][1]);
                cf[((jv+0)*8+p)*2+par] = lo.x; cf[((jv+1)*8+p)*2+par] = lo.y;
                cf[((jv+2)*8+p)*2+par] = hi.x; cf[((jv+3)*8+p)*2+par] = hi.y;
            }
        }
        __syncthreads();

        u64 ar[8], az[8], an[8];
#pragma unroll
        for (int p = 0; p < 8; p++) { ar[p] = 0; az[p] = 0; an[p] = 0; }
        {
            int q = qoff;
            float4 wa = g_D6a[q * 256 + tid];
            float2 wb = g_D6b[q * 256 + tid];
            for (int i = 0; i < 128; i++) {
                int qn = (qoff + i + 1) & 127;
                float4 wan = g_D6a[qn * 256 + tid];
                float2 wbn = g_D6b[qn * 256 + tid];
                DEC_STEP6(2 * q);
                wa = wan; wb = wbn; q = qn;
            }
        }
        {
#pragma unroll
            for (int p = 0; p < 8; p++) {
                float2 fr = u2f(ar[p]), fz = u2f(az[p]), fn = u2f(an[p]);
                float2 cx = ctxp[j * 8 + p];
                float2 hd;
                float pv = prevs[2 * p];
                float r = sigf(pv * dwr + fr.x + br);
                float z = sigf(pv * dwz + fz.x + bz);
                float n = tanhf(pv * dwn + bi + r * (fn.x + bh));
                hd.x = (1.f - z) * n + z * cx.x;
                pv = prevs[2 * p + 1];
                r = sigf(pv * dwr + fr.y + br);
                z = sigf(pv * dwz + fz.y + bz);
                n = tanhf(pv * dwn + bi + r * (fn.y + bh));
                hd.y = (1.f - z) * n + z * cx.y;
                hdp[j * 8 + p] = hd;
            }
        }
        __syncthreads();

        {
            u64 f[8];
#pragma unroll
            for (int p = 0; p < 8; p++) f[p] = 0;
            int q = qoff;
            float2 wf = g_F2[q * 256 + tid];
            for (int i = 0; i < 128; i++) {
                int qn = (qoff + i + 1) & 127;
                float2 wfn = g_F2[qn * 256 + tid];
                const double2* hv0 = reinterpret_cast<const double2*>(hdp + (2 * q) * 8);
                const double2* hv1 = reinterpret_cast<const double2*>(hdp + (2 * q + 1) * 8);
                u64 w0 = pack2(wf.x), w1 = pack2(wf.y);
#pragma unroll
                for (int h = 0; h < 4; h++) {
                    double2 d0 = hv0[h], d1 = hv1[h];
                    fma2(f[2*h],   w0, __double_as_longlong(d0.x));
                    fma2(f[2*h+1], w0, __double_as_longlong(d0.y));
                    fma2(f[2*h],   w1, __double_as_longlong(d1.x));
                    fma2(f[2*h+1], w1, __double_as_longlong(d1.y));
                }
                wf = wfn; q = qn;
            }
#pragma unroll
            for (int p = 0; p < 8; p++) {
                float2 v = u2f(f[p]);
                f1s[(2*p)*FCH + tid]   = fmaxf(v.x + b1, 0.f);
                f1s[(2*p+1)*FCH + tid] = fmaxf(v.y + b1, 0.f);
            }
        }
        __syncthreads();

        {
#pragma unroll
            for (int bb = 0; bb < 2; bb++) {
                int b = wid * 2 + bb;
                float a = 0.f;
#pragma unroll
                for (int qq = 0; qq < 8; qq++)
                    a += f1s[b * FCH + lane + 32 * qq] * w2r[qq];
#pragma unroll
                for (int o = 16; o > 0; o >>= 1) a += __shfl_xor_sync(0xffffffffu, a, o);
                if (lane == 0) {
                    float v = a + fb;
                    out[(size_t)(B0 + b) * OL + step] = v;
                    prevs[b] = v;
                }
            }
        }
        __syncthreads();
    }
}

extern "C" void kernel_launch(void* const* d_in, const int* in_sizes, int n_in,
                              void* d_out, int out_size) {
    const float* x      = (const float*)d_in[0];
    const float* h      = (const float*)d_in[1];
    const float* eWih   = (const float*)d_in[2];
    const float* eWhh   = (const float*)d_in[3];
    const float* ebih   = (const float*)d_in[4];
    const float* ebhh   = (const float*)d_in[5];
    const float* dWih   = (const float*)d_in[6];
    const float* dWhh   = (const float*)d_in[7];
    const float* dbih   = (const float*)d_in[8];
    const float* dbhh   = (const float*)d_in[9];
    const float* wq     = (const float*)d_in[10];
    const float* bq     = (const float*)d_in[11];
    const float* fc1W   = (const float*)d_in[12];
    const float* fc1b   = (const float*)d_in[13];
    const float* fc2W   = (const float*)d_in[14];
    const float* fc2b   = (const float*)d_in[15];
    float* out = (float*)d_out;

    prep_kernel<<<256, 256>>>(x, eWih, eWhh, ebih, ebhh, dWhh, dbih, dbhh, fc1W);
    enc_all_kernel<<<BB / BME, 256>>>(x, h, wq, bq);
    dec_all_kernel<<<BB / BMD, 256>>>(dWih, fc1b, fc2W, fc2b, out);
}